// round 13
// baseline (speedup 1.0000x reference)
#include <cuda_runtime.h>
#include <cuda_fp16.h>
#include <math.h>
#include <stdint.h>

#define S_LEN 2048
#define NTOK  4096
#define HDIM  64
#define NEGBIG -1e9f

// ===================== PTX helpers ==========================================
__device__ __forceinline__ void mma16816(float* c, const uint32_t* a,
                                         uint32_t b0, uint32_t b1) {
    asm volatile(
        "mma.sync.aligned.m16n8k16.row.col.f32.f16.f16.f32 "
        "{%0,%1,%2,%3}, {%4,%5,%6,%7}, {%8,%9}, {%0,%1,%2,%3};"
        : "+f"(c[0]), "+f"(c[1]), "+f"(c[2]), "+f"(c[3])
        : "r"(a[0]), "r"(a[1]), "r"(a[2]), "r"(a[3]), "r"(b0), "r"(b1));
}
__device__ __forceinline__ void ldsm_x4(uint32_t* r, uint32_t addr) {
    asm volatile("ldmatrix.sync.aligned.m8n8.x4.shared.b16 {%0,%1,%2,%3}, [%4];"
                 : "=r"(r[0]), "=r"(r[1]), "=r"(r[2]), "=r"(r[3]) : "r"(addr));
}
__device__ __forceinline__ void ldsm_x4_t(uint32_t* r, uint32_t addr) {
    asm volatile("ldmatrix.sync.aligned.m8n8.x4.trans.shared.b16 {%0,%1,%2,%3}, [%4];"
                 : "=r"(r[0]), "=r"(r[1]), "=r"(r[2]), "=r"(r[3]) : "r"(addr));
}
__device__ __forceinline__ uint32_t smem_u32(const void* p) {
    uint32_t a;
    asm("{ .reg .u64 t; cvta.to.shared.u64 t, %1; cvt.u32.u64 %0, t; }"
        : "=r"(a) : "l"(p));
    return a;
}
__device__ __forceinline__ void cp16(uint32_t dst, const void* src) {
    asm volatile("cp.async.cg.shared.global [%0], [%1], 16;" :: "r"(dst), "l"(src));
}
#define CP_COMMIT() asm volatile("cp.async.commit_group;" ::: "memory")
#define CP_WAIT0()  asm volatile("cp.async.wait_group 0;" ::: "memory")

// ===================== scratch ==============================================
__device__ __align__(16) float g_obuf [NTOK*1536];
__device__ __align__(16) float g_gatec[NTOK*512];
__device__ __align__(16) float g_gatet[NTOK*512];
__device__ __align__(16) float g_imp  [NTOK];
__device__ int   g_tidx [128];

__device__ __align__(16) __half g_xh[NTOK*512];
__device__ __align__(16) __half g_qkvh[NTOK*1536], g_qkvl[NTOK*1536];
__device__ __align__(16) __half g_qch[NTOK*512];
__device__ __align__(16) __half g_qth[NTOK*512];
__device__ __align__(16) __half g_aLh[NTOK*512];
__device__ __align__(16) __half g_aCh[NTOK*512];
__device__ __align__(16) __half g_aTh[NTOK*512];
__device__ __align__(16) __half g_ch[384*512];
__device__ __align__(16) __half g_sh[128*512];
__device__ __align__(16) __half g_kch[384*512], g_kcl[384*512];
__device__ __align__(16) __half g_vch[384*512];
__device__ __align__(16) __half g_kth[128*512], g_ktl[128*512];
__device__ __align__(16) __half g_vth[128*512];
__device__ __align__(16) __half g_wh[7168*512];

// ===================== fused x-prep: convert + pool + imp ===================
__global__ __launch_bounds__(512) void xprep_kernel(
    const float* __restrict__ x, const float* __restrict__ Wimp,
    const float* __restrict__ bimp,
    __half* __restrict__ xh, __half* __restrict__ ch, float* __restrict__ imp)
{
    __shared__ float wred[16][8];
    const int g = blockIdx.x;
    const int b = g >> 8, p = g & 255;
    const int d = threadIdx.x;
    const int lane = d & 31, wid = d >> 5;
    const float w = Wimp[d];

    float psum = 0.f, part[8];
#pragma unroll
    for (int r = 0; r < 8; r++) {
        size_t row = (size_t)(b * S_LEN + p * 8 + r);
        float v = x[row * 512 + d];
        xh[row * 512 + d] = __float2half(v);
        psum += v;
        part[r] = v * w;
    }
    if (p < 192) {
        size_t off = (size_t)(b * 192 + p) * 512 + d;
        ch[off] = __float2half(psum * 0.125f);
    }
#pragma unroll
    for (int r = 0; r < 8; r++) {
        float t = part[r];
#pragma unroll
        for (int off = 16; off; off >>= 1)
            t += __shfl_xor_sync(0xffffffffu, t, off);
        if (!lane) wred[wid][r] = t;
    }
    __syncthreads();
    if (d < 8) {
        float s = 0.f;
#pragma unroll
        for (int ww = 0; ww < 16; ww++) s += wred[ww][d];
        imp[b * S_LEN + p * 8 + d] = s + bimp[0];
    }
}

// ===================== weight converter (fp16 hi only, transposed) ==========
struct WSeg { const float* W; __half* hi; int M; int blk; };
struct WBatch { WSeg s[12]; int n; };

__global__ __launch_bounds__(256) void conv_w(WBatch bt)
{
    __shared__ float ts[32][33];
    int b = blockIdx.x, si = 0;
    while (si < bt.n - 1 && b >= bt.s[si].blk) { b -= bt.s[si].blk; si++; }
    const float* __restrict__ W = bt.s[si].W;
    const int M = bt.s[si].M;
    const int ntn = M >> 5;
    const int tk = (b / ntn) * 32, tn = (b % ntn) * 32;
    const int tx = threadIdx.x & 31, ty = threadIdx.x >> 5;
#pragma unroll
    for (int i = 0; i < 4; i++)
        ts[ty + 8 * i][tx] = W[(size_t)(tk + ty + 8 * i) * M + tn + tx];
    __syncthreads();
#pragma unroll
    for (int i = 0; i < 4; i++) {
        int n = tn + ty + 8 * i, k = tk + tx;
        bt.s[si].hi[(size_t)n * 512 + k] = __float2half(ts[tx][ty + 8 * i]);
    }
}

// ===================== HMMA GEMM v8: 64-wide k-chunks (latency cover) =======
struct MSeg {
    const __half *Ah, *Bh;
    const float* bias;
    float* C; __half *Ch, *Cl;
    int tx, ty, epi, Mout;
};
struct MBatch { MSeg s[9]; int n; };

#define SSTR 72
#define ARR  (128 * SSTR)

__global__ __launch_bounds__(256, 2) void mma_gemm(MBatch bt)
{
    extern __shared__ __half gsm[];   // [2 buf][2 arr][128*SSTR]

    int t = blockIdx.x, si = 0;
    while (si < bt.n - 1 && t >= bt.s[si].tx * bt.s[si].ty) {
        t -= bt.s[si].tx * bt.s[si].ty; si++;
    }
    const MSeg sg = bt.s[si];
    const int col0 = (t % sg.tx) * 128, row0 = (t / sg.tx) * 128;
    const __half* __restrict__ srcs[2] = { sg.Ah, sg.Bh };
    const int rbase[2] = { row0, col0 };

    const int tid = threadIdx.x, wid = tid >> 5, lane = tid & 31;
    const int wr = wid & 3, wc = wid >> 2;
    const int lr = lane >> 2, lc = (lane & 3) * 2;

    float acc[2][8][4];
#pragma unroll
    for (int mt = 0; mt < 2; mt++)
#pragma unroll
        for (int nt = 0; nt < 8; nt++)
#pragma unroll
            for (int j = 0; j < 4; j++) acc[mt][nt][j] = 0.f;

    // one 64-wide k-chunk: A(128x64) + B(128x64) = 2048 uint4, 8 per thread
    auto load_chunk = [&](int d, int kc) {
#pragma unroll
        for (int i = 0; i < 8; i++) {
            int idx = i * 256 + tid;
            int a = idx >> 10, u = idx & 1023;
            int r = u >> 3, cg = u & 7;
            uint32_t dst = smem_u32(gsm + (d * 2 + a) * ARR + r * SSTR + cg * 8);
            cp16(dst, srcs[a] + (size_t)(rbase[a] + r) * 512 + kc + cg * 8);
        }
        CP_COMMIT();
    };

    const int a_row = (lane & 7) + ((lane >> 3) & 1) * 8;
    const int a_col = (lane >> 4) * 8;
    const int b_row = (lane & 7) + ((lane >> 4) & 1) * 8;
    const int b_col = ((lane >> 3) & 1) * 8;

    load_chunk(0, 0);

    for (int c = 0; c < 8; c++) {
        CP_WAIT0();
        __syncthreads();
        if (c + 1 < 8) load_chunk((c + 1) & 1, (c + 1) * 64);

        const int d = c & 1;
        __half* bufAh = gsm + (d * 2 + 0) * ARR;
        __half* bufBh = gsm + (d * 2 + 1) * ARR;

#pragma unroll
        for (int ks = 0; ks < 4; ks++) {
            const int k0 = ks * 16;
            uint32_t af[2][4];
#pragma unroll
            for (int mt = 0; mt < 2; mt++)
                ldsm_x4(af[mt], smem_u32(bufAh + (wr * 32 + mt * 16 + a_row) * SSTR + k0 + a_col));
#pragma unroll
            for (int pr = 0; pr < 4; pr++) {
                uint32_t bh[4];
                ldsm_x4(bh, smem_u32(bufBh + (wc * 64 + pr * 16 + b_row) * SSTR + k0 + b_col));
#pragma unroll
                for (int half = 0; half < 2; half++) {
                    int nt = pr * 2 + half;
                    mma16816(acc[0][nt], af[0], bh[half * 2], bh[half * 2 + 1]);
                    mma16816(acc[1][nt], af[1], bh[half * 2], bh[half * 2 + 1]);
                }
            }
        }
    }

    const float* __restrict__ bias = sg.bias;
    const int Mout = sg.Mout, epi = sg.epi;
#pragma unroll
    for (int mt = 0; mt < 2; mt++) {
        int r = row0 + wr * 32 + mt * 16 + lr;
#pragma unroll
        for (int nt = 0; nt < 8; nt++) {
            int c = col0 + wc * 64 + nt * 8 + lc;
            float b0 = __ldg(bias + c), b1 = __ldg(bias + c + 1);
            float v0 = acc[mt][nt][0] + b0, v1 = acc[mt][nt][1] + b1;
            float v2 = acc[mt][nt][2] + b0, v3 = acc[mt][nt][3] + b1;
            size_t o0 = (size_t)r * Mout + c;
            size_t o1 = (size_t)(r + 8) * Mout + c;
            if (epi == 0) {
                *(float2*)(sg.C + o0) = make_float2(v0, v1);
                *(float2*)(sg.C + o1) = make_float2(v2, v3);
            } else if (epi == 1) {
                *(float2*)(sg.C + o0) = make_float2(
                    1.f / (1.f + expf(-v0)), 1.f / (1.f + expf(-v1)));
                *(float2*)(sg.C + o1) = make_float2(
                    1.f / (1.f + expf(-v2)), 1.f / (1.f + expf(-v3)));
            } else if (epi == 3 || epi == 5) {
                if (epi == 3) { v0 *= 0.125f; v1 *= 0.125f; v2 *= 0.125f; v3 *= 0.125f; }
                *(__half2*)(sg.Ch + o0) = __halves2half2(__float2half(v0), __float2half(v1));
                *(__half2*)(sg.Ch + o1) = __halves2half2(__float2half(v2), __float2half(v3));
            } else {
                bool wlo = (epi == 2) || (c >= 512 && c < 1024);
                if (epi == 4 && c < 512) {
                    v0 *= 0.125f; v1 *= 0.125f; v2 *= 0.125f; v3 *= 0.125f;
                }
                __half h0 = __float2half(v0), h1 = __float2half(v1);
                __half h2 = __float2half(v2), h3 = __float2half(v3);
                *(__half2*)(sg.Ch + o0) = __halves2half2(h0, h1);
                *(__half2*)(sg.Ch + o1) = __halves2half2(h2, h3);
                if (wlo) {
                    *(__half2*)(sg.Cl + o0) = __halves2half2(
                        __float2half(v0 - __half2float(h0)),
                        __float2half(v1 - __half2float(h1)));
                    *(__half2*)(sg.Cl + o1) = __halves2half2(
                        __float2half(v2 - __half2float(h2)),
                        __float2half(v3 - __half2float(h3)));
                }
            }
        }
    }
}

// ===================== attention v2 (unchanged from R12) ====================
#define A2STR 72

struct AttnParams {
    const __half *Qh[3], *Kh[3], *Kl[3], *Vh[3];
    __half *Oh[3];
    int qs[3], ks[3], nk[3];
    const int* tidx;
};

__global__ __launch_bounds__(256) void attn_mma(AttnParams P)
{
    extern __shared__ char dynsm[];
    __half* sQh = (__half*)dynsm;
    __half* sKh = sQh + 64 * A2STR;
    __half* sKl = sKh + 64 * A2STR;
    __half* sVh = sKl + 64 * A2STR;
    int*   pos = (int*)(sVh + 64 * A2STR);
    float* bm  = (float*)(pos + 64);
    float* bs  = bm + 128;
    float* obuf = (float*)sKh;

    const int mode = blockIdx.z >> 1, b = blockIdx.z & 1;
    const int h = blockIdx.y, q0 = blockIdx.x * 64;
    const int tid = threadIdx.x, wid = tid >> 5, lane = tid & 31;
    const int wr = wid & 3, wc = wid >> 2;
    const int lr = lane >> 2, lc = (lane & 3) * 2;
    const int r0 = wr * 16 + lr, r1 = r0 + 8;
    const int qq0 = q0 + r0, qq1 = q0 + r1;

    const int a_row = (lane & 7) + ((lane >> 3) & 1) * 8;
    const int a_col = (lane >> 4) * 8;
    const int b_row = (lane & 7) + ((lane >> 4) & 1) * 8;
    const int b_col = ((lane >> 3) & 1) * 8;
    const int v_row = (lane & 7) + ((lane >> 3) & 1) * 8;
    const int v_col = ((lane >> 4) & 1) * 8;

    const __half* Qh = P.Qh[mode];
    const __half* Kh = P.Kh[mode]; const __half* Kl = P.Kl[mode];
    const __half* Vh = P.Vh[mode];
    const int qs = P.qs[mode], ks = P.ks[mode], nk = P.nk[mode];

    for (int idx = tid; idx < 64 * 8; idx += 256) {
        int r = idx >> 3, d0 = (idx & 7) * 8;
        size_t g = (size_t)(b * S_LEN + q0 + r) * qs + h * HDIM + d0;
        *(uint4*)(sQh + r * A2STR + d0) = *(const uint4*)(Qh + g);
    }

    float oacc[8][4];
#pragma unroll
    for (int nb = 0; nb < 8; nb++)
#pragma unroll
        for (int j = 0; j < 4; j++) oacc[nb][j] = 0.f;

    float m0 = -INFINITY, m1 = -INFINITY, l0 = 0.f, l1 = 0.f;

    int kt0 = 0, ktend = nk;
    if (mode == 0) { kt0 = (q0 > 511) ? ((q0 - 511) & ~63) : 0; ktend = q0 + 64; }

    for (int kt = kt0; kt < ktend; kt += 64) {
        __syncthreads();
        for (int idx = tid; idx < 64 * 8; idx += 256) {
            int r = idx >> 3, d0 = (idx & 7) * 8;
            size_t g = (size_t)(b * nk + kt + r) * ks + h * HDIM + d0;
            *(uint4*)(sKh + r * A2STR + d0) = *(const uint4*)(Kh + g);
            *(uint4*)(sKl + r * A2STR + d0) = *(const uint4*)(Kl + g);
            *(uint4*)(sVh + r * A2STR + d0) = *(const uint4*)(Vh + g);
        }
        if (tid < 64) {
            int j = kt + tid;
            pos[tid] = (mode == 0) ? j : (mode == 1 ? (j + 1) * 8 : P.tidx[b * 64 + j]);
        }
        __syncthreads();

        float sacc[4][4];
#pragma unroll
        for (int nt = 0; nt < 4; nt++)
#pragma unroll
            for (int j = 0; j < 4; j++) sacc[nt][j] = 0.f;
#pragma unroll
        for (int kss = 0; kss < 4; kss++) {
            const int k0 = kss * 16;
            uint32_t qf[4];
            ldsm_x4(qf, smem_u32(sQh + (wr * 16 + a_row) * A2STR + k0 + a_col));
#pragma unroll
            for (int pr = 0; pr < 2; pr++) {
                uint32_t kh[4];
                ldsm_x4(kh, smem_u32(sKh + (wc * 32 + pr * 16 + b_row) * A2STR + k0 + b_col));
#pragma unroll
                for (int half = 0; half < 2; half++)
                    mma16816(sacc[pr * 2 + half], qf, kh[half * 2], kh[half * 2 + 1]);
            }
#pragma unroll
            for (int pr = 0; pr < 2; pr++) {
                uint32_t kl[4];
                ldsm_x4(kl, smem_u32(sKl + (wc * 32 + pr * 16 + b_row) * A2STR + k0 + b_col));
#pragma unroll
                for (int half = 0; half < 2; half++)
                    mma16816(sacc[pr * 2 + half], qf, kl[half * 2], kl[half * 2 + 1]);
            }
        }

        float bx0 = -INFINITY, bx1 = -INFINITY;
#pragma unroll
        for (int nt = 0; nt < 4; nt++) {
#pragma unroll
            for (int ci = 0; ci < 2; ci++) {
                int p = pos[wc * 32 + nt * 8 + lc + ci];
                bool v0 = (mode == 0) ? ((unsigned)(qq0 - p) < 512u) : (qq0 >= p);
                bool v1 = (mode == 0) ? ((unsigned)(qq1 - p) < 512u) : (qq1 >= p);
                if (!v0) sacc[nt][ci] = NEGBIG;
                if (!v1) sacc[nt][2 + ci] = NEGBIG;
                bx0 = fmaxf(bx0, sacc[nt][ci]);
                bx1 = fmaxf(bx1, sacc[nt][2 + ci]);
            }
        }
        bx0 = fmaxf(bx0, __shfl_xor_sync(0xffffffffu, bx0, 1));
        bx0 = fmaxf(bx0, __shfl_xor_sync(0xffffffffu, bx0, 2));
        bx1 = fmaxf(bx1, __shfl_xor_sync(0xffffffffu, bx1, 1));
        bx1 = fmaxf(bx1, __shfl_xor_sync(0xffffffffu, bx1, 2));
        if ((lane & 3) == 0) { bm[r0 * 2 + wc] = bx0; bm[r1 * 2 + wc] = bx1; }
        __syncthreads();

        float mn0 = fmaxf(m0, fmaxf(bm[r0 * 2], bm[r0 * 2 + 1]));
        float mn1 = fmaxf(m1, fmaxf(bm[r1 * 2], bm[r1 * 2 + 1]));

        uint32_t pr0[4], pr1[4];
        float lt0 = 0.f, lt1 = 0.f;
#pragma unroll
        for (int nt = 0; nt < 4; nt++) {
            float e0 = expf(sacc[nt][0] - mn0), e1 = expf(sacc[nt][1] - mn0);
            float e2 = expf(sacc[nt][2] - mn1), e3 = expf(sacc[nt][3] - mn1);
            lt0 += e0 + e1; lt1 += e2 + e3;
            __half2 hp0 = __halves2half2(__float2half(e0), __float2half(e1));
            __half2 hp1 = __halves2half2(__float2half(e2), __float2half(e3));
            pr0[nt] = *(uint32_t*)&hp0;
            pr1[nt] = *(uint32_t*)&hp1;
        }
        lt0 += __shfl_xor_sync(0xffffffffu, lt0, 1);
        lt0 += __shfl_xor_sync(0xffffffffu, lt0, 2);
        lt1 += __shfl_xor_sync(0xffffffffu, lt1, 1);
        lt1 += __shfl_xor_sync(0xffffffffu, lt1, 2);
        if ((lane & 3) == 0) { bs[r0 * 2 + wc] = lt0; bs[r1 * 2 + wc] = lt1; }

        float al0 = expf(m0 - mn0), al1 = expf(m1 - mn1);
        m0 = mn0; m1 = mn1;
#pragma unroll
        for (int nb = 0; nb < 8; nb++) {
            oacc[nb][0] *= al0; oacc[nb][1] *= al0;
            oacc[nb][2] *= al1; oacc[nb][3] *= al1;
        }
        __syncthreads();
        l0 = l0 * al0 + bs[r0 * 2] + bs[r0 * 2 + 1];
        l1 = l1 * al1 + bs[r1 * 2] + bs[r1 * 2 + 1];

#pragma unroll
        for (int kb = 0; kb < 2; kb++) {
            uint32_t af[4] = { pr0[2 * kb], pr1[2 * kb], pr0[2 * kb + 1], pr1[2 * kb + 1] };
            const int krow = wc * 32 + kb * 16;
#pragma unroll
            for (int vt = 0; vt < 4; vt++) {
                uint32_t vh[4];
                ldsm_x4_t(vh, smem_u32(sVh + (krow + v_row) * A2STR + vt * 16 + v_col));
                mma16816(oacc[vt * 2],     af, vh[0], vh[1]);
                mma16816(oacc[vt * 2 + 1], af, vh[2], vh[3]);
            }
        }
    }

    __syncthreads();
    if (wc == 0) {
#pragma unroll
        for (int nb = 0; nb < 8; nb++) {
            *(float2*)(obuf + r0 * 66 + nb * 8 + lc) = make_float2(oacc[nb][0], oacc[nb][1]);
            *(float2*)(obuf + r1 * 66 + nb * 8 + lc) = make_float2(oacc[nb][2], oacc[nb][3]);
        }
    }
    __syncthreads();
    if (wc == 1) {
        float i0 = 1.f / l0, i1 = 1.f / l1;
        __half* Oh = P.Oh[mode];
#pragma unroll
        for (int nb = 0; nb < 8; nb++) {
            float2 p0 = *(const float2*)(obuf + r0 * 66 + nb * 8 + lc);
            float2 p1 = *(const float2*)(obuf + r1 * 66 + nb * 8 + lc);
            int c = h * HDIM + nb * 8 + lc;
            size_t o0 = (size_t)(b * S_LEN + qq0) * 512 + c;
            size_t o1 = (size_t)(b * S_LEN + qq1) * 512 + c;
            *(__half2*)(Oh + o0) = __halves2half2(
                __float2half((p0.x + oacc[nb][0]) * i0),
                __float2half((p0.y + oacc[nb][1]) * i0));
            *(__half2*)(Oh + o1) = __halves2half2(
                __float2half((p1.x + oacc[nb][2]) * i1),
                __float2half((p1.y + oacc[nb][3]) * i1));
        }
    }
}

// ===================== fused topk + gather ==================================
__global__ __launch_bounds__(256) void topk_gather(
    const float* __restrict__ imp, const float* __restrict__ x,
    int* __restrict__ tidx, __half* __restrict__ sh)
{
    int b = blockIdx.x;
    __shared__ float v[2048];
    __shared__ float wv[8];
    __shared__ int   wi[8];
    __shared__ int   sel[64];
    const int tid = threadIdx.x, lane = tid & 31, wid = tid >> 5;

    for (int i = tid; i < 2048; i += 256) v[i] = imp[b * 2048 + i];
    __syncthreads();

    for (int r = 0; r < 64; r++) {
        float bv = -INFINITY; int bi = 0x7fffffff;
        for (int i = tid; i < 2048; i += 256) {
            float xv = v[i];
            if (xv > bv) { bv = xv; bi = i; }
        }
#pragma unroll
        for (int off = 16; off; off >>= 1) {
            float ov = __shfl_xor_sync(0xffffffffu, bv, off);
            int   oi = __shfl_xor_sync(0xffffffffu, bi, off);
            if (ov > bv || (ov == bv && oi < bi)) { bv = ov; bi = oi; }
        }
        if (!lane) { wv[wid] = bv; wi[wid] = bi; }
        __syncthreads();
        if (wid == 0) {
            float cv = (lane < 8) ? wv[lane] : -INFINITY;
            int   ci = (lane < 8) ? wi[lane] : 0x7fffffff;
#pragma unroll
            for (int off = 4; off; off >>= 1) {
                float ov = __shfl_xor_sync(0xffffffffu, cv, off);
                int   oi = __shfl_xor_sync(0xffffffffu, ci, off);
                if (ov > cv || (ov == cv && oi < ci)) { cv = ov; ci = oi; }
            }
            if (!lane) { sel[r] = ci; tidx[b * 64 + r] = ci; v[ci] = -INFINITY; }
        }
        __syncthreads();
    }

    for (int r = 0; r < 64; r++) {
        int src = sel[r];
        for (int d = tid; d < 512; d += 256)
            sh[(size_t)(b * 64 + r) * 512 + d] =
                __float2half(x[(size_t)(b * S_LEN + src) * 512 + d]);
    }
}

__global__ void combine_kernel(const float* __restrict__ b0, const float* __restrict__ bC,
                               const float* __restrict__ bT, const float* __restrict__ gc,
                               const float* __restrict__ gt, float* __restrict__ out)
{
    int i = (blockIdx.x * 256 + threadIdx.x) * 4;
    float4 v0 = *(const float4*)(b0 + i);
    float4 vC = *(const float4*)(bC + i);
    float4 vT = *(const float4*)(bT + i);
    float4 c = *(const float4*)(gc + i);
    float4 t = *(const float4*)(gt + i);
    v0.x += c.x * vC.x + t.x * vT.x;
    v0.y += c.y * vC.y + t.y * vT.y;
    v0.z += c.z * vC.z + t.z * vT.z;
    v0.w += c.w * vC.w + t.w * vT.w;
    *(float4*)(out + i) = v0;
}

// ===================== launch ===============================================
extern "C" void kernel_launch(void* const* d_in, const int* in_sizes, int n_in,
                              void* d_out, int out_size)
{
    const float* x    = (const float*)d_in[0];
    const float* Wqkv = (const float*)d_in[1];  const float* bqkv = (const float*)d_in[2];
    const float* Wlo  = (const float*)d_in[3];  const float* blo  = (const float*)d_in[4];
    const float* Wcq  = (const float*)d_in[5];  const float* bcq  = (const float*)d_in[6];
    const float* Wck  = (const float*)d_in[7];  const float* bck  = (const float*)d_in[8];
    const float* Wcv  = (const float*)d_in[9];  const float* bcv  = (const float*)d_in[10];
    const float* Wco  = (const float*)d_in[11]; const float* bco  = (const float*)d_in[12];
    const float* Wgc  = (const float*)d_in[13]; const float* bgc  = (const float*)d_in[14];
    const float* Wimp = (const float*)d_in[15]; const float* bimp = (const float*)d_in[16];
    const float* Wtq  = (const float*)d_in[17]; const float* btq  = (const float*)d_in[18];
    const float* Wtk  = (const float*)d_in[19]; const float* btk  = (const float*)d_in[20];
    const float* Wtv  = (const float*)d_in[21]; const float* btv  = (const float*)d_in[22];
    const float* Wto  = (const float*)d_in[23]; const float* bto  = (const float*)d_in[24];
    const float* Wgt  = (const float*)d_in[25]; const float* bgt  = (const float*)d_in[26];
    float* out = (float*)d_out;

    float *obuf, *gatec, *gatet, *imp;
    int* tidx;
    __half *xh, *qkvh, *qkvl, *qch, *qth, *aLh, *aCh, *aTh;
    __half *ch, *sh, *kch, *kcl, *vch, *kth, *ktl, *vth, *wh;
    cudaGetSymbolAddress((void**)&obuf,  g_obuf);
    cudaGetSymbolAddress((void**)&gatec, g_gatec);
    cudaGetSymbolAddress((void**)&gatet, g_gatet);
    cudaGetSymbolAddress((void**)&imp,   g_imp);
    cudaGetSymbolAddress((void**)&tidx,  g_tidx);
    cudaGetSymbolAddress((void**)&xh,   g_xh);
    cudaGetSymbolAddress((void**)&qkvh, g_qkvh); cudaGetSymbolAddress((void**)&qkvl, g_qkvl);
    cudaGetSymbolAddress((void**)&qch,  g_qch);
    cudaGetSymbolAddress((void**)&qth,  g_qth);
    cudaGetSymbolAddress((void**)&aLh,  g_aLh);
    cudaGetSymbolAddress((void**)&aCh,  g_aCh);
    cudaGetSymbolAddress((void**)&aTh,  g_aTh);
    cudaGetSymbolAddress((void**)&ch,   g_ch);
    cudaGetSymbolAddress((void**)&sh,   g_sh);
    cudaGetSymbolAddress((void**)&kch,  g_kch);  cudaGetSymbolAddress((void**)&kcl,  g_kcl);
    cudaGetSymbolAddress((void**)&vch,  g_vch);
    cudaGetSymbolAddress((void**)&kth,  g_kth);  cudaGetSymbolAddress((void**)&ktl,  g_ktl);
    cudaGetSymbolAddress((void**)&vth,  g_vth);
    cudaGetSymbolAddress((void**)&wh,   g_wh);

    const int ATTN_SMEM = 4 * 64 * A2STR * 2 + 64 * 4 + 2 * 128 * 4;
    cudaFuncSetAttribute(attn_mma, cudaFuncAttributeMaxDynamicSharedMemorySize, ATTN_SMEM);
    const int GEMM_SMEM = 2 * 2 * ARR * 2;   // 73728
    cudaFuncSetAttribute(mma_gemm, cudaFuncAttributeMaxDynamicSharedMemorySize, GEMM_SMEM);

    const int O_QKV = 0,    O_LO = 1536, O_CQ = 2048, O_CK = 2560, O_CV = 3072,
              O_CO = 3584,  O_GC = 4096, O_TQ = 4608, O_TK = 5120, O_TV = 5632,
              O_TO = 6144,  O_GT = 6656;
    #define WH(o) (wh + (size_t)(o) * 512)

    {
        WBatch wb;
        wb.s[0]  = {Wqkv, WH(O_QKV), 1536, 768};
        wb.s[1]  = {Wlo,  WH(O_LO),  512, 256};
        wb.s[2]  = {Wcq,  WH(O_CQ),  512, 256};
        wb.s[3]  = {Wck,  WH(O_CK),  512, 256};
        wb.s[4]  = {Wcv,  WH(O_CV),  512, 256};
        wb.s[5]  = {Wco,  WH(O_CO),  512, 256};
        wb.s[6]  = {Wgc,  WH(O_GC),  512, 256};
        wb.s[7]  = {Wtq,  WH(O_TQ),  512, 256};
        wb.s[8]  = {Wtk,  WH(O_TK),  512, 256};
        wb.s[9]  = {Wtv,  WH(O_TV),  512, 256};
        wb.s[10] = {Wto,  WH(O_TO),  512, 256};
        wb.s[11] = {Wgt,  WH(O_GT),  512, 256};
        wb.n = 12;
        conv_w<<<768 + 11 * 256, 256>>>(wb);
    }
    xprep_kernel<<<512, 512>>>(x, Wimp, bimp, xh, ch, imp);
    topk_gather<<<2, 256>>>(imp, x, tidx, sh);

    {
        MBatch mb;
        mb.s[0] = {xh, WH(O_QKV), bqkv, nullptr, qkvh, qkvl, 12, 32, 4, 1536};
        mb.s[1] = {xh, WH(O_CQ),  bcq,  nullptr, qch,  nullptr, 4, 32, 3, 512};
        mb.s[2] = {xh, WH(O_GC),  bgc,  gatec,  nullptr, nullptr, 4, 32, 1, 512};
        mb.s[3] = {xh, WH(O_TQ),  btq,  nullptr, qth,  nullptr, 4, 32, 3, 512};
        mb.s[4] = {xh, WH(O_GT),  bgt,  gatet,  nullptr, nullptr, 4, 32, 1, 512};
        mb.s[5] = {ch, WH(O_CK),  bck,  nullptr, kch,  kcl, 4, 3, 2, 512};
        mb.s[6] = {ch, WH(O_CV),  bcv,  nullptr, vch,  nullptr, 4, 3, 5, 512};
        mb.s[7] = {sh, WH(O_TK),  btk,  nullptr, kth,  ktl, 4, 1, 2, 512};
        mb.s[8] = {sh, WH(O_TV),  btv,  nullptr, vth,  nullptr, 4, 1, 5, 512};
        mb.n = 9;
        mma_gemm<<<928, 256, GEMM_SMEM>>>(mb);
    }

    {
        AttnParams P;
        P.Qh[0] = qkvh;
        P.Kh[0] = qkvh + 512;  P.Kl[0] = qkvl + 512;
        P.Vh[0] = qkvh + 1024;
        P.Oh[0] = aLh; P.qs[0] = 1536; P.ks[0] = 1536; P.nk[0] = 2048;
        P.Qh[1] = qch; P.Kh[1] = kch; P.Kl[1] = kcl; P.Vh[1] = vch;
        P.Oh[1] = aCh; P.qs[1] = 512; P.ks[1] = 512; P.nk[1] = 192;
        P.Qh[2] = qth; P.Kh[2] = kth; P.Kl[2] = ktl; P.Vh[2] = vth;
        P.Oh[2] = aTh; P.qs[2] = 512; P.ks[2] = 512; P.nk[2] = 64;
        P.tidx = tidx;
        attn_mma<<<dim3(32, 8, 6), 256, ATTN_SMEM>>>(P);
    }

    float* buf0 = obuf;
    float* bufC = obuf + (size_t)NTOK * 512;
    float* bufT = obuf + (size_t)NTOK * 1024;
    {
        MBatch mb;
        mb.s[0] = {aLh, WH(O_LO), blo, buf0, nullptr, nullptr, 4, 32, 0, 512};
        mb.s[1] = {aCh, WH(O_CO), bco, bufC, nullptr, nullptr, 4, 32, 0, 512};
        mb.s[2] = {aTh, WH(O_TO), bto, bufT, nullptr, nullptr, 4, 32, 0, 512};
        mb.n = 3;
        mma_gemm<<<384, 256, GEMM_SMEM>>>(mb);
    }
    combine_kernel<<<NTOK * 512 / 1024, 256>>>(buf0, bufC, bufT, gatec, gatet, out);
}

// round 14
// speedup vs baseline: 1.0414x; 1.0414x over previous
#include <cuda_runtime.h>
#include <cuda_fp16.h>
#include <math.h>
#include <stdint.h>

#define S_LEN 2048
#define NTOK  4096
#define HDIM  64
#define NEGBIG -1e9f

// ===================== PTX helpers ==========================================
__device__ __forceinline__ void mma16816(float* c, const uint32_t* a,
                                         uint32_t b0, uint32_t b1) {
    asm volatile(
        "mma.sync.aligned.m16n8k16.row.col.f32.f16.f16.f32 "
        "{%0,%1,%2,%3}, {%4,%5,%6,%7}, {%8,%9}, {%0,%1,%2,%3};"
        : "+f"(c[0]), "+f"(c[1]), "+f"(c[2]), "+f"(c[3])
        : "r"(a[0]), "r"(a[1]), "r"(a[2]), "r"(a[3]), "r"(b0), "r"(b1));
}
__device__ __forceinline__ void ldsm_x4(uint32_t* r, uint32_t addr) {
    asm volatile("ldmatrix.sync.aligned.m8n8.x4.shared.b16 {%0,%1,%2,%3}, [%4];"
                 : "=r"(r[0]), "=r"(r[1]), "=r"(r[2]), "=r"(r[3]) : "r"(addr));
}
__device__ __forceinline__ void ldsm_x4_t(uint32_t* r, uint32_t addr) {
    asm volatile("ldmatrix.sync.aligned.m8n8.x4.trans.shared.b16 {%0,%1,%2,%3}, [%4];"
                 : "=r"(r[0]), "=r"(r[1]), "=r"(r[2]), "=r"(r[3]) : "r"(addr));
}
__device__ __forceinline__ uint32_t smem_u32(const void* p) {
    uint32_t a;
    asm("{ .reg .u64 t; cvta.to.shared.u64 t, %1; cvt.u32.u64 %0, t; }"
        : "=r"(a) : "l"(p));
    return a;
}
__device__ __forceinline__ void cp16(uint32_t dst, const void* src) {
    asm volatile("cp.async.cg.shared.global [%0], [%1], 16;" :: "r"(dst), "l"(src));
}
#define CP_COMMIT() asm volatile("cp.async.commit_group;" ::: "memory")
#define CP_WAIT0()  asm volatile("cp.async.wait_group 0;" ::: "memory")

// ===================== scratch ==============================================
__device__ __align__(16) float g_obuf [NTOK*1536];
__device__ __align__(16) float g_gatec[NTOK*512];
__device__ __align__(16) float g_gatet[NTOK*512];
__device__ __align__(16) float g_imp  [NTOK];
__device__ int   g_tidx [128];

__device__ __align__(16) __half g_xh[NTOK*512];
__device__ __align__(16) __half g_qkvh[NTOK*1536], g_qkvl[NTOK*1536];
__device__ __align__(16) __half g_qch[NTOK*512];
__device__ __align__(16) __half g_qth[NTOK*512];
__device__ __align__(16) __half g_aLh[NTOK*512];
__device__ __align__(16) __half g_aCh[NTOK*512];
__device__ __align__(16) __half g_aTh[NTOK*512];
__device__ __align__(16) __half g_ch[384*512];
__device__ __align__(16) __half g_sh[128*512];
__device__ __align__(16) __half g_kch[384*512], g_kcl[384*512];
__device__ __align__(16) __half g_vch[384*512];
__device__ __align__(16) __half g_kth[128*512], g_ktl[128*512];
__device__ __align__(16) __half g_vth[128*512];
__device__ __align__(16) __half g_wh[7168*512];

// ===================== fused x-prep: convert + pool + imp ===================
__global__ __launch_bounds__(512) void xprep_kernel(
    const float* __restrict__ x, const float* __restrict__ Wimp,
    const float* __restrict__ bimp,
    __half* __restrict__ xh, __half* __restrict__ ch, float* __restrict__ imp)
{
    __shared__ float wred[16][8];
    const int g = blockIdx.x;
    const int b = g >> 8, p = g & 255;
    const int d = threadIdx.x;
    const int lane = d & 31, wid = d >> 5;
    const float w = Wimp[d];

    float psum = 0.f, part[8];
#pragma unroll
    for (int r = 0; r < 8; r++) {
        size_t row = (size_t)(b * S_LEN + p * 8 + r);
        float v = x[row * 512 + d];
        xh[row * 512 + d] = __float2half(v);
        psum += v;
        part[r] = v * w;
    }
    if (p < 192) {
        size_t off = (size_t)(b * 192 + p) * 512 + d;
        ch[off] = __float2half(psum * 0.125f);
    }
#pragma unroll
    for (int r = 0; r < 8; r++) {
        float t = part[r];
#pragma unroll
        for (int off = 16; off; off >>= 1)
            t += __shfl_xor_sync(0xffffffffu, t, off);
        if (!lane) wred[wid][r] = t;
    }
    __syncthreads();
    if (d < 8) {
        float s = 0.f;
#pragma unroll
        for (int ww = 0; ww < 16; ww++) s += wred[ww][d];
        imp[b * S_LEN + p * 8 + d] = s + bimp[0];
    }
}

// ===================== weight converter (fp16 hi only, transposed) ==========
struct WSeg { const float* W; __half* hi; int M; int blk; };
struct WBatch { WSeg s[12]; int n; };

__global__ __launch_bounds__(256) void conv_w(WBatch bt)
{
    __shared__ float ts[32][33];
    int b = blockIdx.x, si = 0;
    while (si < bt.n - 1 && b >= bt.s[si].blk) { b -= bt.s[si].blk; si++; }
    const float* __restrict__ W = bt.s[si].W;
    const int M = bt.s[si].M;
    const int ntn = M >> 5;
    const int tk = (b / ntn) * 32, tn = (b % ntn) * 32;
    const int tx = threadIdx.x & 31, ty = threadIdx.x >> 5;
#pragma unroll
    for (int i = 0; i < 4; i++)
        ts[ty + 8 * i][tx] = W[(size_t)(tk + ty + 8 * i) * M + tn + tx];
    __syncthreads();
#pragma unroll
    for (int i = 0; i < 4; i++) {
        int n = tn + ty + 8 * i, k = tk + tx;
        bt.s[si].hi[(size_t)n * 512 + k] = __float2half(ts[tx][ty + 8 * i]);
    }
}

// ===================== HMMA GEMM v9: 128x64 tiles, 3 CTA/SM =================
struct MSeg {
    const __half *Ah, *Bh;
    const float* bias;
    float* C; __half *Ch, *Cl;
    int tx, ty, epi, Mout;   // tx in 64-col tiles, ty in 128-row tiles
};
struct MBatch { MSeg s[9]; int n; };

#define SSTR  72
#define A_ARR (128 * SSTR)
#define B_ARR (64 * SSTR)
#define BUFSZ (A_ARR + B_ARR)

__global__ __launch_bounds__(256, 3) void mma_gemm(MBatch bt)
{
    extern __shared__ __half gsm[];   // [2 buf][A(128x64) | B(64x64)]

    int t = blockIdx.x, si = 0;
    while (si < bt.n - 1 && t >= bt.s[si].tx * bt.s[si].ty) {
        t -= bt.s[si].tx * bt.s[si].ty; si++;
    }
    const MSeg sg = bt.s[si];
    const int col0 = (t % sg.tx) * 64, row0 = (t / sg.tx) * 128;
    const __half* __restrict__ srcs[2] = { sg.Ah, sg.Bh };
    const int rbase[2] = { row0, col0 };

    const int tid = threadIdx.x, wid = tid >> 5, lane = tid & 31;
    const int wr = wid & 3, wc = wid >> 2;
    const int lr = lane >> 2, lc = (lane & 3) * 2;

    float acc[2][4][4];
#pragma unroll
    for (int mt = 0; mt < 2; mt++)
#pragma unroll
        for (int nt = 0; nt < 4; nt++)
#pragma unroll
            for (int j = 0; j < 4; j++) acc[mt][nt][j] = 0.f;

    // one 64-wide k-chunk: A(128x64)=1024 uint4 + B(64x64)=512 uint4, 6/thread
    auto load_chunk = [&](int d, int kc) {
#pragma unroll
        for (int i = 0; i < 6; i++) {
            int idx = i * 256 + tid;
            int a = (idx >= 1024);
            int u = a ? idx - 1024 : idx;
            int r = u >> 3, cg = u & 7;
            uint32_t dst = smem_u32(gsm + d * BUFSZ + a * A_ARR + r * SSTR + cg * 8);
            cp16(dst, srcs[a] + (size_t)(rbase[a] + r) * 512 + kc + cg * 8);
        }
        CP_COMMIT();
    };

    const int a_row = (lane & 7) + ((lane >> 3) & 1) * 8;
    const int a_col = (lane >> 4) * 8;
    const int b_row = (lane & 7) + ((lane >> 4) & 1) * 8;
    const int b_col = ((lane >> 3) & 1) * 8;

    load_chunk(0, 0);

    for (int c = 0; c < 8; c++) {
        CP_WAIT0();
        __syncthreads();
        if (c + 1 < 8) load_chunk((c + 1) & 1, (c + 1) * 64);

        __half* bufA = gsm + (c & 1) * BUFSZ;
        __half* bufB = bufA + A_ARR;

#pragma unroll
        for (int ks = 0; ks < 4; ks++) {
            const int k0 = ks * 16;
            uint32_t af[2][4];
#pragma unroll
            for (int mt = 0; mt < 2; mt++)
                ldsm_x4(af[mt], smem_u32(bufA + (wr * 32 + mt * 16 + a_row) * SSTR + k0 + a_col));
#pragma unroll
            for (int pr = 0; pr < 2; pr++) {
                uint32_t bh[4];
                ldsm_x4(bh, smem_u32(bufB + (wc * 32 + pr * 16 + b_row) * SSTR + k0 + b_col));
#pragma unroll
                for (int half = 0; half < 2; half++) {
                    int nt = pr * 2 + half;
                    mma16816(acc[0][nt], af[0], bh[half * 2], bh[half * 2 + 1]);
                    mma16816(acc[1][nt], af[1], bh[half * 2], bh[half * 2 + 1]);
                }
            }
        }
    }

    const float* __restrict__ bias = sg.bias;
    const int Mout = sg.Mout, epi = sg.epi;
#pragma unroll
    for (int mt = 0; mt < 2; mt++) {
        int r = row0 + wr * 32 + mt * 16 + lr;
#pragma unroll
        for (int nt = 0; nt < 4; nt++) {
            int c = col0 + wc * 32 + nt * 8 + lc;
            float b0 = __ldg(bias + c), b1 = __ldg(bias + c + 1);
            float v0 = acc[mt][nt][0] + b0, v1 = acc[mt][nt][1] + b1;
            float v2 = acc[mt][nt][2] + b0, v3 = acc[mt][nt][3] + b1;
            size_t o0 = (size_t)r * Mout + c;
            size_t o1 = (size_t)(r + 8) * Mout + c;
            if (epi == 0) {
                *(float2*)(sg.C + o0) = make_float2(v0, v1);
                *(float2*)(sg.C + o1) = make_float2(v2, v3);
            } else if (epi == 1) {
                *(float2*)(sg.C + o0) = make_float2(
                    1.f / (1.f + expf(-v0)), 1.f / (1.f + expf(-v1)));
                *(float2*)(sg.C + o1) = make_float2(
                    1.f / (1.f + expf(-v2)), 1.f / (1.f + expf(-v3)));
            } else if (epi == 3 || epi == 5) {
                if (epi == 3) { v0 *= 0.125f; v1 *= 0.125f; v2 *= 0.125f; v3 *= 0.125f; }
                *(__half2*)(sg.Ch + o0) = __halves2half2(__float2half(v0), __float2half(v1));
                *(__half2*)(sg.Ch + o1) = __halves2half2(__float2half(v2), __float2half(v3));
            } else {
                bool wlo = (epi == 2) || (c >= 512 && c < 1024);
                if (epi == 4 && c < 512) {
                    v0 *= 0.125f; v1 *= 0.125f; v2 *= 0.125f; v3 *= 0.125f;
                }
                __half h0 = __float2half(v0), h1 = __float2half(v1);
                __half h2 = __float2half(v2), h3 = __float2half(v3);
                *(__half2*)(sg.Ch + o0) = __halves2half2(h0, h1);
                *(__half2*)(sg.Ch + o1) = __halves2half2(h2, h3);
                if (wlo) {
                    *(__half2*)(sg.Cl + o0) = __halves2half2(
                        __float2half(v0 - __half2float(h0)),
                        __float2half(v1 - __half2float(h1)));
                    *(__half2*)(sg.Cl + o1) = __halves2half2(
                        __float2half(v2 - __half2float(h2)),
                        __float2half(v3 - __half2float(h3)));
                }
            }
        }
    }
}

// ===================== attention v2 (unchanged, passing) ====================
#define A2STR 72

struct AttnParams {
    const __half *Qh[3], *Kh[3], *Kl[3], *Vh[3];
    __half *Oh[3];
    int qs[3], ks[3], nk[3];
    const int* tidx;
};

__global__ __launch_bounds__(256) void attn_mma(AttnParams P)
{
    extern __shared__ char dynsm[];
    __half* sQh = (__half*)dynsm;
    __half* sKh = sQh + 64 * A2STR;
    __half* sKl = sKh + 64 * A2STR;
    __half* sVh = sKl + 64 * A2STR;
    int*   pos = (int*)(sVh + 64 * A2STR);
    float* bm  = (float*)(pos + 64);
    float* bs  = bm + 128;
    float* obuf = (float*)sKh;

    const int mode = blockIdx.z >> 1, b = blockIdx.z & 1;
    const int h = blockIdx.y, q0 = blockIdx.x * 64;
    const int tid = threadIdx.x, wid = tid >> 5, lane = tid & 31;
    const int wr = wid & 3, wc = wid >> 2;
    const int lr = lane >> 2, lc = (lane & 3) * 2;
    const int r0 = wr * 16 + lr, r1 = r0 + 8;
    const int qq0 = q0 + r0, qq1 = q0 + r1;

    const int a_row = (lane & 7) + ((lane >> 3) & 1) * 8;
    const int a_col = (lane >> 4) * 8;
    const int b_row = (lane & 7) + ((lane >> 4) & 1) * 8;
    const int b_col = ((lane >> 3) & 1) * 8;
    const int v_row = (lane & 7) + ((lane >> 3) & 1) * 8;
    const int v_col = ((lane >> 4) & 1) * 8;

    const __half* Qh = P.Qh[mode];
    const __half* Kh = P.Kh[mode]; const __half* Kl = P.Kl[mode];
    const __half* Vh = P.Vh[mode];
    const int qs = P.qs[mode], ks = P.ks[mode], nk = P.nk[mode];

    for (int idx = tid; idx < 64 * 8; idx += 256) {
        int r = idx >> 3, d0 = (idx & 7) * 8;
        size_t g = (size_t)(b * S_LEN + q0 + r) * qs + h * HDIM + d0;
        *(uint4*)(sQh + r * A2STR + d0) = *(const uint4*)(Qh + g);
    }

    float oacc[8][4];
#pragma unroll
    for (int nb = 0; nb < 8; nb++)
#pragma unroll
        for (int j = 0; j < 4; j++) oacc[nb][j] = 0.f;

    float m0 = -INFINITY, m1 = -INFINITY, l0 = 0.f, l1 = 0.f;

    int kt0 = 0, ktend = nk;
    if (mode == 0) { kt0 = (q0 > 511) ? ((q0 - 511) & ~63) : 0; ktend = q0 + 64; }

    for (int kt = kt0; kt < ktend; kt += 64) {
        __syncthreads();
        for (int idx = tid; idx < 64 * 8; idx += 256) {
            int r = idx >> 3, d0 = (idx & 7) * 8;
            size_t g = (size_t)(b * nk + kt + r) * ks + h * HDIM + d0;
            *(uint4*)(sKh + r * A2STR + d0) = *(const uint4*)(Kh + g);
            *(uint4*)(sKl + r * A2STR + d0) = *(const uint4*)(Kl + g);
            *(uint4*)(sVh + r * A2STR + d0) = *(const uint4*)(Vh + g);
        }
        if (tid < 64) {
            int j = kt + tid;
            pos[tid] = (mode == 0) ? j : (mode == 1 ? (j + 1) * 8 : P.tidx[b * 64 + j]);
        }
        __syncthreads();

        float sacc[4][4];
#pragma unroll
        for (int nt = 0; nt < 4; nt++)
#pragma unroll
            for (int j = 0; j < 4; j++) sacc[nt][j] = 0.f;
#pragma unroll
        for (int kss = 0; kss < 4; kss++) {
            const int k0 = kss * 16;
            uint32_t qf[4];
            ldsm_x4(qf, smem_u32(sQh + (wr * 16 + a_row) * A2STR + k0 + a_col));
#pragma unroll
            for (int pr = 0; pr < 2; pr++) {
                uint32_t kh[4];
                ldsm_x4(kh, smem_u32(sKh + (wc * 32 + pr * 16 + b_row) * A2STR + k0 + b_col));
#pragma unroll
                for (int half = 0; half < 2; half++)
                    mma16816(sacc[pr * 2 + half], qf, kh[half * 2], kh[half * 2 + 1]);
            }
#pragma unroll
            for (int pr = 0; pr < 2; pr++) {
                uint32_t kl[4];
                ldsm_x4(kl, smem_u32(sKl + (wc * 32 + pr * 16 + b_row) * A2STR + k0 + b_col));
#pragma unroll
                for (int half = 0; half < 2; half++)
                    mma16816(sacc[pr * 2 + half], qf, kl[half * 2], kl[half * 2 + 1]);
            }
        }

        float bx0 = -INFINITY, bx1 = -INFINITY;
#pragma unroll
        for (int nt = 0; nt < 4; nt++) {
#pragma unroll
            for (int ci = 0; ci < 2; ci++) {
                int p = pos[wc * 32 + nt * 8 + lc + ci];
                bool v0 = (mode == 0) ? ((unsigned)(qq0 - p) < 512u) : (qq0 >= p);
                bool v1 = (mode == 0) ? ((unsigned)(qq1 - p) < 512u) : (qq1 >= p);
                if (!v0) sacc[nt][ci] = NEGBIG;
                if (!v1) sacc[nt][2 + ci] = NEGBIG;
                bx0 = fmaxf(bx0, sacc[nt][ci]);
                bx1 = fmaxf(bx1, sacc[nt][2 + ci]);
            }
        }
        bx0 = fmaxf(bx0, __shfl_xor_sync(0xffffffffu, bx0, 1));
        bx0 = fmaxf(bx0, __shfl_xor_sync(0xffffffffu, bx0, 2));
        bx1 = fmaxf(bx1, __shfl_xor_sync(0xffffffffu, bx1, 1));
        bx1 = fmaxf(bx1, __shfl_xor_sync(0xffffffffu, bx1, 2));
        if ((lane & 3) == 0) { bm[r0 * 2 + wc] = bx0; bm[r1 * 2 + wc] = bx1; }
        __syncthreads();

        float mn0 = fmaxf(m0, fmaxf(bm[r0 * 2], bm[r0 * 2 + 1]));
        float mn1 = fmaxf(m1, fmaxf(bm[r1 * 2], bm[r1 * 2 + 1]));

        uint32_t pr0[4], pr1[4];
        float lt0 = 0.f, lt1 = 0.f;
#pragma unroll
        for (int nt = 0; nt < 4; nt++) {
            float e0 = expf(sacc[nt][0] - mn0), e1 = expf(sacc[nt][1] - mn0);
            float e2 = expf(sacc[nt][2] - mn1), e3 = expf(sacc[nt][3] - mn1);
            lt0 += e0 + e1; lt1 += e2 + e3;
            __half2 hp0 = __halves2half2(__float2half(e0), __float2half(e1));
            __half2 hp1 = __halves2half2(__float2half(e2), __float2half(e3));
            pr0[nt] = *(uint32_t*)&hp0;
            pr1[nt] = *(uint32_t*)&hp1;
        }
        lt0 += __shfl_xor_sync(0xffffffffu, lt0, 1);
        lt0 += __shfl_xor_sync(0xffffffffu, lt0, 2);
        lt1 += __shfl_xor_sync(0xffffffffu, lt1, 1);
        lt1 += __shfl_xor_sync(0xffffffffu, lt1, 2);
        if ((lane & 3) == 0) { bs[r0 * 2 + wc] = lt0; bs[r1 * 2 + wc] = lt1; }

        float al0 = expf(m0 - mn0), al1 = expf(m1 - mn1);
        m0 = mn0; m1 = mn1;
#pragma unroll
        for (int nb = 0; nb < 8; nb++) {
            oacc[nb][0] *= al0; oacc[nb][1] *= al0;
            oacc[nb][2] *= al1; oacc[nb][3] *= al1;
        }
        __syncthreads();
        l0 = l0 * al0 + bs[r0 * 2] + bs[r0 * 2 + 1];
        l1 = l1 * al1 + bs[r1 * 2] + bs[r1 * 2 + 1];

#pragma unroll
        for (int kb = 0; kb < 2; kb++) {
            uint32_t af[4] = { pr0[2 * kb], pr1[2 * kb], pr0[2 * kb + 1], pr1[2 * kb + 1] };
            const int krow = wc * 32 + kb * 16;
#pragma unroll
            for (int vt = 0; vt < 4; vt++) {
                uint32_t vh[4];
                ldsm_x4_t(vh, smem_u32(sVh + (krow + v_row) * A2STR + vt * 16 + v_col));
                mma16816(oacc[vt * 2],     af, vh[0], vh[1]);
                mma16816(oacc[vt * 2 + 1], af, vh[2], vh[3]);
            }
        }
    }

    __syncthreads();
    if (wc == 0) {
#pragma unroll
        for (int nb = 0; nb < 8; nb++) {
            *(float2*)(obuf + r0 * 66 + nb * 8 + lc) = make_float2(oacc[nb][0], oacc[nb][1]);
            *(float2*)(obuf + r1 * 66 + nb * 8 + lc) = make_float2(oacc[nb][2], oacc[nb][3]);
        }
    }
    __syncthreads();
    if (wc == 1) {
        float i0 = 1.f / l0, i1 = 1.f / l1;
        __half* Oh = P.Oh[mode];
#pragma unroll
        for (int nb = 0; nb < 8; nb++) {
            float2 p0 = *(const float2*)(obuf + r0 * 66 + nb * 8 + lc);
            float2 p1 = *(const float2*)(obuf + r1 * 66 + nb * 8 + lc);
            int c = h * HDIM + nb * 8 + lc;
            size_t o0 = (size_t)(b * S_LEN + qq0) * 512 + c;
            size_t o1 = (size_t)(b * S_LEN + qq1) * 512 + c;
            *(__half2*)(Oh + o0) = __halves2half2(
                __float2half((p0.x + oacc[nb][0]) * i0),
                __float2half((p0.y + oacc[nb][1]) * i0));
            *(__half2*)(Oh + o1) = __halves2half2(
                __float2half((p1.x + oacc[nb][2]) * i1),
                __float2half((p1.y + oacc[nb][3]) * i1));
        }
    }
}

// ===================== fused topk + gather ==================================
__global__ __launch_bounds__(256) void topk_gather(
    const float* __restrict__ imp, const float* __restrict__ x,
    int* __restrict__ tidx, __half* __restrict__ sh)
{
    int b = blockIdx.x;
    __shared__ float v[2048];
    __shared__ float wv[8];
    __shared__ int   wi[8];
    __shared__ int   sel[64];
    const int tid = threadIdx.x, lane = tid & 31, wid = tid >> 5;

    for (int i = tid; i < 2048; i += 256) v[i] = imp[b * 2048 + i];
    __syncthreads();

    for (int r = 0; r < 64; r++) {
        float bv = -INFINITY; int bi = 0x7fffffff;
        for (int i = tid; i < 2048; i += 256) {
            float xv = v[i];
            if (xv > bv) { bv = xv; bi = i; }
        }
#pragma unroll
        for (int off = 16; off; off >>= 1) {
            float ov = __shfl_xor_sync(0xffffffffu, bv, off);
            int   oi = __shfl_xor_sync(0xffffffffu, bi, off);
            if (ov > bv || (ov == bv && oi < bi)) { bv = ov; bi = oi; }
        }
        if (!lane) { wv[wid] = bv; wi[wid] = bi; }
        __syncthreads();
        if (wid == 0) {
            float cv = (lane < 8) ? wv[lane] : -INFINITY;
            int   ci = (lane < 8) ? wi[lane] : 0x7fffffff;
#pragma unroll
            for (int off = 4; off; off >>= 1) {
                float ov = __shfl_xor_sync(0xffffffffu, cv, off);
                int   oi = __shfl_xor_sync(0xffffffffu, ci, off);
                if (ov > cv || (ov == cv && oi < ci)) { cv = ov; ci = oi; }
            }
            if (!lane) { sel[r] = ci; tidx[b * 64 + r] = ci; v[ci] = -INFINITY; }
        }
        __syncthreads();
    }

    for (int r = 0; r < 64; r++) {
        int src = sel[r];
        for (int d = tid; d < 512; d += 256)
            sh[(size_t)(b * 64 + r) * 512 + d] =
                __float2half(x[(size_t)(b * S_LEN + src) * 512 + d]);
    }
}

__global__ void combine_kernel(const float* __restrict__ b0, const float* __restrict__ bC,
                               const float* __restrict__ bT, const float* __restrict__ gc,
                               const float* __restrict__ gt, float* __restrict__ out)
{
    int i = (blockIdx.x * 256 + threadIdx.x) * 4;
    float4 v0 = *(const float4*)(b0 + i);
    float4 vC = *(const float4*)(bC + i);
    float4 vT = *(const float4*)(bT + i);
    float4 c = *(const float4*)(gc + i);
    float4 t = *(const float4*)(gt + i);
    v0.x += c.x * vC.x + t.x * vT.x;
    v0.y += c.y * vC.y + t.y * vT.y;
    v0.z += c.z * vC.z + t.z * vT.z;
    v0.w += c.w * vC.w + t.w * vT.w;
    *(float4*)(out + i) = v0;
}

// ===================== launch ===============================================
extern "C" void kernel_launch(void* const* d_in, const int* in_sizes, int n_in,
                              void* d_out, int out_size)
{
    const float* x    = (const float*)d_in[0];
    const float* Wqkv = (const float*)d_in[1];  const float* bqkv = (const float*)d_in[2];
    const float* Wlo  = (const float*)d_in[3];  const float* blo  = (const float*)d_in[4];
    const float* Wcq  = (const float*)d_in[5];  const float* bcq  = (const float*)d_in[6];
    const float* Wck  = (const float*)d_in[7];  const float* bck  = (const float*)d_in[8];
    const float* Wcv  = (const float*)d_in[9];  const float* bcv  = (const float*)d_in[10];
    const float* Wco  = (const float*)d_in[11]; const float* bco  = (const float*)d_in[12];
    const float* Wgc  = (const float*)d_in[13]; const float* bgc  = (const float*)d_in[14];
    const float* Wimp = (const float*)d_in[15]; const float* bimp = (const float*)d_in[16];
    const float* Wtq  = (const float*)d_in[17]; const float* btq  = (const float*)d_in[18];
    const float* Wtk  = (const float*)d_in[19]; const float* btk  = (const float*)d_in[20];
    const float* Wtv  = (const float*)d_in[21]; const float* btv  = (const float*)d_in[22];
    const float* Wto  = (const float*)d_in[23]; const float* bto  = (const float*)d_in[24];
    const float* Wgt  = (const float*)d_in[25]; const float* bgt  = (const float*)d_in[26];
    float* out = (float*)d_out;

    float *obuf, *gatec, *gatet, *imp;
    int* tidx;
    __half *xh, *qkvh, *qkvl, *qch, *qth, *aLh, *aCh, *aTh;
    __half *ch, *sh, *kch, *kcl, *vch, *kth, *ktl, *vth, *wh;
    cudaGetSymbolAddress((void**)&obuf,  g_obuf);
    cudaGetSymbolAddress((void**)&gatec, g_gatec);
    cudaGetSymbolAddress((void**)&gatet, g_gatet);
    cudaGetSymbolAddress((void**)&imp,   g_imp);
    cudaGetSymbolAddress((void**)&tidx,  g_tidx);
    cudaGetSymbolAddress((void**)&xh,   g_xh);
    cudaGetSymbolAddress((void**)&qkvh, g_qkvh); cudaGetSymbolAddress((void**)&qkvl, g_qkvl);
    cudaGetSymbolAddress((void**)&qch,  g_qch);
    cudaGetSymbolAddress((void**)&qth,  g_qth);
    cudaGetSymbolAddress((void**)&aLh,  g_aLh);
    cudaGetSymbolAddress((void**)&aCh,  g_aCh);
    cudaGetSymbolAddress((void**)&aTh,  g_aTh);
    cudaGetSymbolAddress((void**)&ch,   g_ch);
    cudaGetSymbolAddress((void**)&sh,   g_sh);
    cudaGetSymbolAddress((void**)&kch,  g_kch);  cudaGetSymbolAddress((void**)&kcl,  g_kcl);
    cudaGetSymbolAddress((void**)&vch,  g_vch);
    cudaGetSymbolAddress((void**)&kth,  g_kth);  cudaGetSymbolAddress((void**)&ktl,  g_ktl);
    cudaGetSymbolAddress((void**)&vth,  g_vth);
    cudaGetSymbolAddress((void**)&wh,   g_wh);

    const int ATTN_SMEM = 4 * 64 * A2STR * 2 + 64 * 4 + 2 * 128 * 4;
    cudaFuncSetAttribute(attn_mma, cudaFuncAttributeMaxDynamicSharedMemorySize, ATTN_SMEM);
    const int GEMM_SMEM = 2 * BUFSZ * 2;   // 55296
    cudaFuncSetAttribute(mma_gemm, cudaFuncAttributeMaxDynamicSharedMemorySize, GEMM_SMEM);

    const int O_QKV = 0,    O_LO = 1536, O_CQ = 2048, O_CK = 2560, O_CV = 3072,
              O_CO = 3584,  O_GC = 4096, O_TQ = 4608, O_TK = 5120, O_TV = 5632,
              O_TO = 6144,  O_GT = 6656;
    #define WH(o) (wh + (size_t)(o) * 512)

    {
        WBatch wb;
        wb.s[0]  = {Wqkv, WH(O_QKV), 1536, 768};
        wb.s[1]  = {Wlo,  WH(O_LO),  512, 256};
        wb.s[2]  = {Wcq,  WH(O_CQ),  512, 256};
        wb.s[3]  = {Wck,  WH(O_CK),  512, 256};
        wb.s[4]  = {Wcv,  WH(O_CV),  512, 256};
        wb.s[5]  = {Wco,  WH(O_CO),  512, 256};
        wb.s[6]  = {Wgc,  WH(O_GC),  512, 256};
        wb.s[7]  = {Wtq,  WH(O_TQ),  512, 256};
        wb.s[8]  = {Wtk,  WH(O_TK),  512, 256};
        wb.s[9]  = {Wtv,  WH(O_TV),  512, 256};
        wb.s[10] = {Wto,  WH(O_TO),  512, 256};
        wb.s[11] = {Wgt,  WH(O_GT),  512, 256};
        wb.n = 12;
        conv_w<<<768 + 11 * 256, 256>>>(wb);
    }
    xprep_kernel<<<512, 512>>>(x, Wimp, bimp, xh, ch, imp);
    topk_gather<<<2, 256>>>(imp, x, tidx, sh);

    {
        MBatch mb;
        mb.s[0] = {xh, WH(O_QKV), bqkv, nullptr, qkvh, qkvl, 24, 32, 4, 1536};
        mb.s[1] = {xh, WH(O_CQ),  bcq,  nullptr, qch,  nullptr, 8, 32, 3, 512};
        mb.s[2] = {xh, WH(O_GC),  bgc,  gatec,  nullptr, nullptr, 8, 32, 1, 512};
        mb.s[3] = {xh, WH(O_TQ),  btq,  nullptr, qth,  nullptr, 8, 32, 3, 512};
        mb.s[4] = {xh, WH(O_GT),  bgt,  gatet,  nullptr, nullptr, 8, 32, 1, 512};
        mb.s[5] = {ch, WH(O_CK),  bck,  nullptr, kch,  kcl, 8, 3, 2, 512};
        mb.s[6] = {ch, WH(O_CV),  bcv,  nullptr, vch,  nullptr, 8, 3, 5, 512};
        mb.s[7] = {sh, WH(O_TK),  btk,  nullptr, kth,  ktl, 8, 1, 2, 512};
        mb.s[8] = {sh, WH(O_TV),  btv,  nullptr, vth,  nullptr, 8, 1, 5, 512};
        mb.n = 9;
        mma_gemm<<<1856, 256, GEMM_SMEM>>>(mb);
    }

    {
        AttnParams P;
        P.Qh[0] = qkvh;
        P.Kh[0] = qkvh + 512;  P.Kl[0] = qkvl + 512;
        P.Vh[0] = qkvh + 1024;
        P.Oh[0] = aLh; P.qs[0] = 1536; P.ks[0] = 1536; P.nk[0] = 2048;
        P.Qh[1] = qch; P.Kh[1] = kch; P.Kl[1] = kcl; P.Vh[1] = vch;
        P.Oh[1] = aCh; P.qs[1] = 512; P.ks[1] = 512; P.nk[1] = 192;
        P.Qh[2] = qth; P.Kh[2] = kth; P.Kl[2] = ktl; P.Vh[2] = vth;
        P.Oh[2] = aTh; P.qs[2] = 512; P.ks[2] = 512; P.nk[2] = 64;
        P.tidx = tidx;
        attn_mma<<<dim3(32, 8, 6), 256, ATTN_SMEM>>>(P);
    }

    float* buf0 = obuf;
    float* bufC = obuf + (size_t)NTOK * 512;
    float* bufT = obuf + (size_t)NTOK * 1024;
    {
        MBatch mb;
        mb.s[0] = {aLh, WH(O_LO), blo, buf0, nullptr, nullptr, 8, 32, 0, 512};
        mb.s[1] = {aCh, WH(O_CO), bco, bufC, nullptr, nullptr, 8, 32, 0, 512};
        mb.s[2] = {aTh, WH(O_TO), bto, bufT, nullptr, nullptr, 8, 32, 0, 512};
        mb.n = 3;
        mma_gemm<<<768, 256, GEMM_SMEM>>>(mb);
    }
    combine_kernel<<<NTOK * 512 / 1024, 256>>>(buf0, bufC, bufT, gatec, gatet, out);
}

// round 15
// speedup vs baseline: 1.1606x; 1.1144x over previous
#include <cuda_runtime.h>
#include <cuda_fp16.h>
#include <math.h>
#include <stdint.h>

#define S_LEN 2048
#define NTOK  4096
#define HDIM  64
#define NEGBIG -1e9f

// ===================== PTX helpers ==========================================
__device__ __forceinline__ void mma16816(float* c, const uint32_t* a,
                                         uint32_t b0, uint32_t b1) {
    asm volatile(
        "mma.sync.aligned.m16n8k16.row.col.f32.f16.f16.f32 "
        "{%0,%1,%2,%3}, {%4,%5,%6,%7}, {%8,%9}, {%0,%1,%2,%3};"
        : "+f"(c[0]), "+f"(c[1]), "+f"(c[2]), "+f"(c[3])
        : "r"(a[0]), "r"(a[1]), "r"(a[2]), "r"(a[3]), "r"(b0), "r"(b1));
}
__device__ __forceinline__ void ldsm_x4(uint32_t* r, uint32_t addr) {
    asm volatile("ldmatrix.sync.aligned.m8n8.x4.shared.b16 {%0,%1,%2,%3}, [%4];"
                 : "=r"(r[0]), "=r"(r[1]), "=r"(r[2]), "=r"(r[3]) : "r"(addr));
}
__device__ __forceinline__ void ldsm_x4_t(uint32_t* r, uint32_t addr) {
    asm volatile("ldmatrix.sync.aligned.m8n8.x4.trans.shared.b16 {%0,%1,%2,%3}, [%4];"
                 : "=r"(r[0]), "=r"(r[1]), "=r"(r[2]), "=r"(r[3]) : "r"(addr));
}
__device__ __forceinline__ uint32_t smem_u32(const void* p) {
    uint32_t a;
    asm("{ .reg .u64 t; cvta.to.shared.u64 t, %1; cvt.u32.u64 %0, t; }"
        : "=r"(a) : "l"(p));
    return a;
}
__device__ __forceinline__ void cp16(uint32_t dst, const void* src) {
    asm volatile("cp.async.cg.shared.global [%0], [%1], 16;" :: "r"(dst), "l"(src));
}
#define CP_COMMIT() asm volatile("cp.async.commit_group;" ::: "memory")
#define CP_WAIT0()  asm volatile("cp.async.wait_group 0;" ::: "memory")

// ===================== scratch ==============================================
__device__ __align__(16) float g_obuf [NTOK*1536];
__device__ __align__(16) float g_gatec[NTOK*512];
__device__ __align__(16) float g_gatet[NTOK*512];
__device__ __align__(16) float g_imp  [NTOK];
__device__ int   g_tidx [128];

__device__ __align__(16) __half g_xh[NTOK*512];
__device__ __align__(16) __half g_qkvh[NTOK*1536], g_qkvl[NTOK*1536];
__device__ __align__(16) __half g_qch[NTOK*512];
__device__ __align__(16) __half g_qth[NTOK*512];
__device__ __align__(16) __half g_aLh[NTOK*512];
__device__ __align__(16) __half g_aCh[NTOK*512];
__device__ __align__(16) __half g_aTh[NTOK*512];
__device__ __align__(16) __half g_ch[384*512];
__device__ __align__(16) __half g_sh[128*512];
__device__ __align__(16) __half g_kch[384*512], g_kcl[384*512];
__device__ __align__(16) __half g_vch[384*512];
__device__ __align__(16) __half g_kth[128*512], g_ktl[128*512];
__device__ __align__(16) __half g_vth[128*512];
__device__ __align__(16) __half g_wh[7168*512];

// ===================== fused x-prep: convert + pool + imp ===================
__global__ __launch_bounds__(512) void xprep_kernel(
    const float* __restrict__ x, const float* __restrict__ Wimp,
    const float* __restrict__ bimp,
    __half* __restrict__ xh, __half* __restrict__ ch, float* __restrict__ imp)
{
    __shared__ float wred[16][8];
    const int g = blockIdx.x;
    const int b = g >> 8, p = g & 255;
    const int d = threadIdx.x;
    const int lane = d & 31, wid = d >> 5;
    const float w = Wimp[d];

    float psum = 0.f, part[8];
#pragma unroll
    for (int r = 0; r < 8; r++) {
        size_t row = (size_t)(b * S_LEN + p * 8 + r);
        float v = x[row * 512 + d];
        xh[row * 512 + d] = __float2half(v);
        psum += v;
        part[r] = v * w;
    }
    if (p < 192) {
        size_t off = (size_t)(b * 192 + p) * 512 + d;
        ch[off] = __float2half(psum * 0.125f);
    }
#pragma unroll
    for (int r = 0; r < 8; r++) {
        float t = part[r];
#pragma unroll
        for (int off = 16; off; off >>= 1)
            t += __shfl_xor_sync(0xffffffffu, t, off);
        if (!lane) wred[wid][r] = t;
    }
    __syncthreads();
    if (d < 8) {
        float s = 0.f;
#pragma unroll
        for (int ww = 0; ww < 16; ww++) s += wred[ww][d];
        imp[b * S_LEN + p * 8 + d] = s + bimp[0];
    }
}

// ===================== weight converter =====================================
struct WSeg { const float* W; __half* hi; int M; int blk; };
struct WBatch { WSeg s[12]; int n; };

__global__ __launch_bounds__(256) void conv_w(WBatch bt)
{
    __shared__ float ts[32][33];
    int b = blockIdx.x, si = 0;
    while (si < bt.n - 1 && b >= bt.s[si].blk) { b -= bt.s[si].blk; si++; }
    const float* __restrict__ W = bt.s[si].W;
    const int M = bt.s[si].M;
    const int ntn = M >> 5;
    const int tk = (b / ntn) * 32, tn = (b % ntn) * 32;
    const int tx = threadIdx.x & 31, ty = threadIdx.x >> 5;
#pragma unroll
    for (int i = 0; i < 4; i++)
        ts[ty + 8 * i][tx] = W[(size_t)(tk + ty + 8 * i) * M + tn + tx];
    __syncthreads();
#pragma unroll
    for (int i = 0; i < 4; i++) {
        int n = tn + ty + 8 * i, k = tk + tx;
        bt.s[si].hi[(size_t)n * 512 + k] = __float2half(ts[tx][ty + 8 * i]);
    }
}

// ===================== HMMA GEMM v10: 128x64 tiles, low-ALU loads ===========
struct MSeg {
    const __half *Ah, *Bh;
    const float* bias;
    float* C; __half *Ch, *Cl;
    int tx, ty, epi, Mout;
};
struct MBatch { MSeg s[9]; int n; };

#define SSTR  72
#define A_ARR (128 * SSTR)
#define B_ARR (64 * SSTR)
#define BUFSZ (A_ARR + B_ARR)

__global__ __launch_bounds__(256, 3) void mma_gemm(MBatch bt)
{
    extern __shared__ __half gsm[];

    int t = blockIdx.x, si = 0;
    while (si < bt.n - 1 && t >= bt.s[si].tx * bt.s[si].ty) {
        t -= bt.s[si].tx * bt.s[si].ty; si++;
    }
    const MSeg sg = bt.s[si];
    const int col0 = (t % sg.tx) * 64, row0 = (t / sg.tx) * 128;

    const int tid = threadIdx.x, wid = tid >> 5, lane = tid & 31;
    const int wr = wid & 3, wc = wid >> 2;
    const int lr = lane >> 2, lc = (lane & 3) * 2;

    float acc[2][4][4];
#pragma unroll
    for (int mt = 0; mt < 2; mt++)
#pragma unroll
        for (int nt = 0; nt < 4; nt++)
#pragma unroll
            for (int j = 0; j < 4; j++) acc[mt][nt][j] = 0.f;

    // precomputed load addressing (pure pointer adds in the loop)
    const int lrow = tid >> 3, lcol = (tid & 7) * 8;
    const __half* gA = sg.Ah + (size_t)(row0 + lrow) * 512 + lcol;
    const __half* gB = sg.Bh + (size_t)(col0 + lrow) * 512 + lcol;
    const uint32_t sA0 = smem_u32(gsm + lrow * SSTR + lcol);
    const uint32_t sB0 = sA0 + A_ARR * 2;

    auto load_chunk = [&](int d, int kc) {
        uint32_t dA = sA0 + d * (BUFSZ * 2);
        uint32_t dB = sB0 + d * (BUFSZ * 2);
#pragma unroll
        for (int i = 0; i < 4; i++)
            cp16(dA + i * (32 * SSTR * 2), gA + kc + i * (32 * 512));
#pragma unroll
        for (int i = 0; i < 2; i++)
            cp16(dB + i * (32 * SSTR * 2), gB + kc + i * (32 * 512));
        CP_COMMIT();
    };

    const int a_row = (lane & 7) + ((lane >> 3) & 1) * 8;
    const int a_col = (lane >> 4) * 8;
    const int b_row = (lane & 7) + ((lane >> 4) & 1) * 8;
    const int b_col = ((lane >> 3) & 1) * 8;

    const uint32_t aBase0 = smem_u32(gsm + (wr * 32 + a_row) * SSTR + a_col);
    const uint32_t bBase0 = smem_u32(gsm) + A_ARR * 2 +
                            ((wc * 32 + b_row) * SSTR + b_col) * 2;

    load_chunk(0, 0);

    for (int c = 0; c < 8; c++) {
        CP_WAIT0();
        __syncthreads();
        if (c + 1 < 8) load_chunk((c + 1) & 1, (c + 1) * 64);

        const uint32_t aBase = aBase0 + (c & 1) * (BUFSZ * 2);
        const uint32_t bBase = bBase0 + (c & 1) * (BUFSZ * 2);

#pragma unroll
        for (int ks = 0; ks < 4; ks++) {
            const int k0b = ks * 32;   // bytes
            uint32_t af[2][4];
#pragma unroll
            for (int mt = 0; mt < 2; mt++)
                ldsm_x4(af[mt], aBase + mt * (16 * SSTR * 2) + k0b);
#pragma unroll
            for (int pr = 0; pr < 2; pr++) {
                uint32_t bh[4];
                ldsm_x4(bh, bBase + pr * (16 * SSTR * 2) + k0b);
#pragma unroll
                for (int half = 0; half < 2; half++) {
                    int nt = pr * 2 + half;
                    mma16816(acc[0][nt], af[0], bh[half * 2], bh[half * 2 + 1]);
                    mma16816(acc[1][nt], af[1], bh[half * 2], bh[half * 2 + 1]);
                }
            }
        }
    }

    const float* __restrict__ bias = sg.bias;
    const int Mout = sg.Mout, epi = sg.epi;
#pragma unroll
    for (int mt = 0; mt < 2; mt++) {
        int r = row0 + wr * 32 + mt * 16 + lr;
#pragma unroll
        for (int nt = 0; nt < 4; nt++) {
            int c = col0 + wc * 32 + nt * 8 + lc;
            float b0 = __ldg(bias + c), b1 = __ldg(bias + c + 1);
            float v0 = acc[mt][nt][0] + b0, v1 = acc[mt][nt][1] + b1;
            float v2 = acc[mt][nt][2] + b0, v3 = acc[mt][nt][3] + b1;
            size_t o0 = (size_t)r * Mout + c;
            size_t o1 = (size_t)(r + 8) * Mout + c;
            if (epi == 0) {
                *(float2*)(sg.C + o0) = make_float2(v0, v1);
                *(float2*)(sg.C + o1) = make_float2(v2, v3);
            } else if (epi == 1) {
                *(float2*)(sg.C + o0) = make_float2(
                    1.f / (1.f + expf(-v0)), 1.f / (1.f + expf(-v1)));
                *(float2*)(sg.C + o1) = make_float2(
                    1.f / (1.f + expf(-v2)), 1.f / (1.f + expf(-v3)));
            } else if (epi == 3 || epi == 5) {
                if (epi == 3) { v0 *= 0.125f; v1 *= 0.125f; v2 *= 0.125f; v3 *= 0.125f; }
                *(__half2*)(sg.Ch + o0) = __halves2half2(__float2half(v0), __float2half(v1));
                *(__half2*)(sg.Ch + o1) = __halves2half2(__float2half(v2), __float2half(v3));
            } else {
                bool wlo = (epi == 2) || (c >= 512 && c < 1024);
                if (epi == 4 && c < 512) {
                    v0 *= 0.125f; v1 *= 0.125f; v2 *= 0.125f; v3 *= 0.125f;
                }
                __half h0 = __float2half(v0), h1 = __float2half(v1);
                __half h2 = __float2half(v2), h3 = __float2half(v3);
                *(__half2*)(sg.Ch + o0) = __halves2half2(h0, h1);
                *(__half2*)(sg.Ch + o1) = __halves2half2(h2, h3);
                if (wlo) {
                    *(__half2*)(sg.Cl + o0) = __halves2half2(
                        __float2half(v0 - __half2float(h0)),
                        __float2half(v1 - __half2float(h1)));
                    *(__half2*)(sg.Cl + o1) = __halves2half2(
                        __float2half(v2 - __half2float(h2)),
                        __float2half(v3 - __half2float(h3)));
                }
            }
        }
    }
}

// ===================== attention v3: 128-q tiles, warp-local softmax ========
#define A3STR 72

struct AttnParams {
    const __half *Qh[3], *Kh[3], *Kl[3], *Vh[3];
    __half *Oh[3];
    int qs[3], ks[3], nk[3];
    const int* tidx;
};

__global__ __launch_bounds__(256, 2) void attn_mma(AttnParams P)
{
    extern __shared__ char dynsm[];
    __half* sQ  = (__half*)dynsm;            // 128 x A3STR
    __half* sKh = sQ  + 128 * A3STR;
    __half* sKl = sKh + 64 * A3STR;
    __half* sVh = sKl + 64 * A3STR;
    int*    pos = (int*)(sVh + 64 * A3STR);

    const int mode = blockIdx.z >> 1, b = blockIdx.z & 1;
    const int h = blockIdx.y, q0 = blockIdx.x * 128;
    const int tid = threadIdx.x, wid = tid >> 5, lane = tid & 31;
    const int lr = lane >> 2, lc = (lane & 3) * 2;
    const int r0 = wid * 16 + lr, r1 = r0 + 8;
    const int qq0 = q0 + r0, qq1 = q0 + r1;

    const int a_row = (lane & 7) + ((lane >> 3) & 1) * 8;
    const int a_col = (lane >> 4) * 8;
    const int b_row = (lane & 7) + ((lane >> 4) & 1) * 8;
    const int b_col = ((lane >> 3) & 1) * 8;
    const int v_row = (lane & 7) + ((lane >> 3) & 1) * 8;
    const int v_col = ((lane >> 4) & 1) * 8;

    const __half* Qh = P.Qh[mode];
    const __half* Kh = P.Kh[mode]; const __half* Kl = P.Kl[mode];
    const __half* Vh = P.Vh[mode];
    const int qs = P.qs[mode], ks = P.ks[mode], nk = P.nk[mode];

    // load Q tile (128 x 64), 4 uint4 per thread
    {
        int r = tid >> 3, c8 = (tid & 7) * 8;
#pragma unroll
        for (int i = 0; i < 4; i++) {
            int row = r + i * 32;
            *(uint4*)(sQ + row * A3STR + c8) =
                *(const uint4*)(Qh + (size_t)(b * S_LEN + q0 + row) * qs + h * HDIM + c8);
        }
    }
    __syncthreads();

    // Q fragments to registers (16 regs)
    uint32_t qf[4][4];
    {
        uint32_t qb = smem_u32(sQ + (wid * 16 + a_row) * A3STR + a_col);
#pragma unroll
        for (int kss = 0; kss < 4; kss++)
            ldsm_x4(qf[kss], qb + kss * 32);
    }

    float oacc[8][4];
#pragma unroll
    for (int nt = 0; nt < 8; nt++)
#pragma unroll
        for (int j = 0; j < 4; j++) oacc[nt][j] = 0.f;

    float m0 = -INFINITY, m1 = -INFINITY, l0 = 0.f, l1 = 0.f;

    int kt0 = 0, ktend = nk;
    if (mode == 0) { kt0 = (q0 > 511) ? ((q0 - 511) & ~63) : 0; ktend = q0 + 128; }

    const int klr = tid >> 3, klc = (tid & 7) * 8;   // K/V loader coords

    for (int kt = kt0; kt < ktend; kt += 64) {
        __syncthreads();
        {
            size_t gb = (size_t)(b * nk + kt + klr) * ks + h * HDIM + klc;
            size_t step = (size_t)32 * ks;
#pragma unroll
            for (int i = 0; i < 2; i++) {
                *(uint4*)(sKh + (klr + i * 32) * A3STR + klc) = *(const uint4*)(Kh + gb + i * step);
                *(uint4*)(sKl + (klr + i * 32) * A3STR + klc) = *(const uint4*)(Kl + gb + i * step);
                *(uint4*)(sVh + (klr + i * 32) * A3STR + klc) = *(const uint4*)(Vh + gb + i * step);
            }
        }
        if (tid < 64) {
            int j = kt + tid;
            pos[tid] = (mode == 0) ? j : (mode == 1 ? (j + 1) * 8 : P.tidx[b * 64 + j]);
        }
        __syncthreads();

        // ---- S = Q K^T (K hi+lo), warp-local rows ----
        float sacc[8][4];
#pragma unroll
        for (int nt = 0; nt < 8; nt++)
#pragma unroll
            for (int j = 0; j < 4; j++) sacc[nt][j] = 0.f;

        const uint32_t khb = smem_u32(sKh + b_row * A3STR + b_col);
        const uint32_t klb = smem_u32(sKl + b_row * A3STR + b_col);
#pragma unroll
        for (int kss = 0; kss < 4; kss++) {
            const int k0b = kss * 32;
#pragma unroll
            for (int pr = 0; pr < 4; pr++) {
                uint32_t kh[4];
                ldsm_x4(kh, khb + pr * (16 * A3STR * 2) + k0b);
                mma16816(sacc[2 * pr],     qf[kss], kh[0], kh[1]);
                mma16816(sacc[2 * pr + 1], qf[kss], kh[2], kh[3]);
            }
#pragma unroll
            for (int pr = 0; pr < 4; pr++) {
                uint32_t kl[4];
                ldsm_x4(kl, klb + pr * (16 * A3STR * 2) + k0b);
                mma16816(sacc[2 * pr],     qf[kss], kl[0], kl[1]);
                mma16816(sacc[2 * pr + 1], qf[kss], kl[2], kl[3]);
            }
        }

        // ---- mask + warp-local max ----
        float bx0 = -INFINITY, bx1 = -INFINITY;
#pragma unroll
        for (int nt = 0; nt < 8; nt++) {
#pragma unroll
            for (int ci = 0; ci < 2; ci++) {
                int p = pos[nt * 8 + lc + ci];
                bool v0 = (mode == 0) ? ((unsigned)(qq0 - p) < 512u) : (qq0 >= p);
                bool v1 = (mode == 0) ? ((unsigned)(qq1 - p) < 512u) : (qq1 >= p);
                if (!v0) sacc[nt][ci] = NEGBIG;
                if (!v1) sacc[nt][2 + ci] = NEGBIG;
                bx0 = fmaxf(bx0, sacc[nt][ci]);
                bx1 = fmaxf(bx1, sacc[nt][2 + ci]);
            }
        }
        bx0 = fmaxf(bx0, __shfl_xor_sync(0xffffffffu, bx0, 1));
        bx0 = fmaxf(bx0, __shfl_xor_sync(0xffffffffu, bx0, 2));
        bx1 = fmaxf(bx1, __shfl_xor_sync(0xffffffffu, bx1, 1));
        bx1 = fmaxf(bx1, __shfl_xor_sync(0xffffffffu, bx1, 2));
        float mn0 = fmaxf(m0, bx0), mn1 = fmaxf(m1, bx1);

        // ---- exp + pack P as A-frags ----
        uint32_t pr0[8], pr1[8];
        float lt0 = 0.f, lt1 = 0.f;
#pragma unroll
        for (int nt = 0; nt < 8; nt++) {
            float e0 = expf(sacc[nt][0] - mn0), e1 = expf(sacc[nt][1] - mn0);
            float e2 = expf(sacc[nt][2] - mn1), e3 = expf(sacc[nt][3] - mn1);
            lt0 += e0 + e1; lt1 += e2 + e3;
            __half2 hp0 = __halves2half2(__float2half(e0), __float2half(e1));
            __half2 hp1 = __halves2half2(__float2half(e2), __float2half(e3));
            pr0[nt] = *(uint32_t*)&hp0;
            pr1[nt] = *(uint32_t*)&hp1;
        }
        lt0 += __shfl_xor_sync(0xffffffffu, lt0, 1);
        lt0 += __shfl_xor_sync(0xffffffffu, lt0, 2);
        lt1 += __shfl_xor_sync(0xffffffffu, lt1, 1);
        lt1 += __shfl_xor_sync(0xffffffffu, lt1, 2);

        float al0 = expf(m0 - mn0), al1 = expf(m1 - mn1);
        m0 = mn0; m1 = mn1;
        l0 = l0 * al0 + lt0;
        l1 = l1 * al1 + lt1;
#pragma unroll
        for (int nt = 0; nt < 8; nt++) {
            oacc[nt][0] *= al0; oacc[nt][1] *= al0;
            oacc[nt][2] *= al1; oacc[nt][3] *= al1;
        }

        // ---- O += P V ----
        const uint32_t vb = smem_u32(sVh + v_row * A3STR + v_col);
#pragma unroll
        for (int kb = 0; kb < 4; kb++) {
            uint32_t af[4] = { pr0[2 * kb], pr1[2 * kb], pr0[2 * kb + 1], pr1[2 * kb + 1] };
#pragma unroll
            for (int vt = 0; vt < 4; vt++) {
                uint32_t vh[4];
                ldsm_x4_t(vh, vb + kb * (16 * A3STR * 2) + vt * 32);
                mma16816(oacc[2 * vt],     af, vh[0], vh[1]);
                mma16816(oacc[2 * vt + 1], af, vh[2], vh[3]);
            }
        }
    }

    // ---- epilogue (warp-local, direct) ----
    float i0 = 1.f / l0, i1 = 1.f / l1;
    __half* Oh = P.Oh[mode];
#pragma unroll
    for (int nt = 0; nt < 8; nt++) {
        int c = h * HDIM + nt * 8 + lc;
        size_t o0 = (size_t)(b * S_LEN + qq0) * 512 + c;
        size_t o1 = (size_t)(b * S_LEN + qq1) * 512 + c;
        *(__half2*)(Oh + o0) = __halves2half2(
            __float2half(oacc[nt][0] * i0), __float2half(oacc[nt][1] * i0));
        *(__half2*)(Oh + o1) = __halves2half2(
            __float2half(oacc[nt][2] * i1), __float2half(oacc[nt][3] * i1));
    }
}

// ===================== fused topk + gather ==================================
__global__ __launch_bounds__(256) void topk_gather(
    const float* __restrict__ imp, const float* __restrict__ x,
    int* __restrict__ tidx, __half* __restrict__ sh)
{
    int b = blockIdx.x;
    __shared__ float v[2048];
    __shared__ float wv[8];
    __shared__ int   wi[8];
    __shared__ int   sel[64];
    const int tid = threadIdx.x, lane = tid & 31, wid = tid >> 5;

    for (int i = tid; i < 2048; i += 256) v[i] = imp[b * 2048 + i];
    __syncthreads();

    for (int r = 0; r < 64; r++) {
        float bv = -INFINITY; int bi = 0x7fffffff;
        for (int i = tid; i < 2048; i += 256) {
            float xv = v[i];
            if (xv > bv) { bv = xv; bi = i; }
        }
#pragma unroll
        for (int off = 16; off; off >>= 1) {
            float ov = __shfl_xor_sync(0xffffffffu, bv, off);
            int   oi = __shfl_xor_sync(0xffffffffu, bi, off);
            if (ov > bv || (ov == bv && oi < bi)) { bv = ov; bi = oi; }
        }
        if (!lane) { wv[wid] = bv; wi[wid] = bi; }
        __syncthreads();
        if (wid == 0) {
            float cv = (lane < 8) ? wv[lane] : -INFINITY;
            int   ci = (lane < 8) ? wi[lane] : 0x7fffffff;
#pragma unroll
            for (int off = 4; off; off >>= 1) {
                float ov = __shfl_xor_sync(0xffffffffu, cv, off);
                int   oi = __shfl_xor_sync(0xffffffffu, ci, off);
                if (ov > cv || (ov == cv && oi < ci)) { cv = ov; ci = oi; }
            }
            if (!lane) { sel[r] = ci; tidx[b * 64 + r] = ci; v[ci] = -INFINITY; }
        }
        __syncthreads();
    }

    for (int r = 0; r < 64; r++) {
        int src = sel[r];
        for (int d = tid; d < 512; d += 256)
            sh[(size_t)(b * 64 + r) * 512 + d] =
                __float2half(x[(size_t)(b * S_LEN + src) * 512 + d]);
    }
}

__global__ void combine_kernel(const float* __restrict__ b0, const float* __restrict__ bC,
                               const float* __restrict__ bT, const float* __restrict__ gc,
                               const float* __restrict__ gt, float* __restrict__ out)
{
    int i = (blockIdx.x * 256 + threadIdx.x) * 4;
    float4 v0 = *(const float4*)(b0 + i);
    float4 vC = *(const float4*)(bC + i);
    float4 vT = *(const float4*)(bT + i);
    float4 c = *(const float4*)(gc + i);
    float4 t = *(const float4*)(gt + i);
    v0.x += c.x * vC.x + t.x * vT.x;
    v0.y += c.y * vC.y + t.y * vT.y;
    v0.z += c.z * vC.z + t.z * vT.z;
    v0.w += c.w * vC.w + t.w * vT.w;
    *(float4*)(out + i) = v0;
}

// ===================== launch ===============================================
extern "C" void kernel_launch(void* const* d_in, const int* in_sizes, int n_in,
                              void* d_out, int out_size)
{
    const float* x    = (const float*)d_in[0];
    const float* Wqkv = (const float*)d_in[1];  const float* bqkv = (const float*)d_in[2];
    const float* Wlo  = (const float*)d_in[3];  const float* blo  = (const float*)d_in[4];
    const float* Wcq  = (const float*)d_in[5];  const float* bcq  = (const float*)d_in[6];
    const float* Wck  = (const float*)d_in[7];  const float* bck  = (const float*)d_in[8];
    const float* Wcv  = (const float*)d_in[9];  const float* bcv  = (const float*)d_in[10];
    const float* Wco  = (const float*)d_in[11]; const float* bco  = (const float*)d_in[12];
    const float* Wgc  = (const float*)d_in[13]; const float* bgc  = (const float*)d_in[14];
    const float* Wimp = (const float*)d_in[15]; const float* bimp = (const float*)d_in[16];
    const float* Wtq  = (const float*)d_in[17]; const float* btq  = (const float*)d_in[18];
    const float* Wtk  = (const float*)d_in[19]; const float* btk  = (const float*)d_in[20];
    const float* Wtv  = (const float*)d_in[21]; const float* btv  = (const float*)d_in[22];
    const float* Wto  = (const float*)d_in[23]; const float* bto  = (const float*)d_in[24];
    const float* Wgt  = (const float*)d_in[25]; const float* bgt  = (const float*)d_in[26];
    float* out = (float*)d_out;

    float *obuf, *gatec, *gatet, *imp;
    int* tidx;
    __half *xh, *qkvh, *qkvl, *qch, *qth, *aLh, *aCh, *aTh;
    __half *ch, *sh, *kch, *kcl, *vch, *kth, *ktl, *vth, *wh;
    cudaGetSymbolAddress((void**)&obuf,  g_obuf);
    cudaGetSymbolAddress((void**)&gatec, g_gatec);
    cudaGetSymbolAddress((void**)&gatet, g_gatet);
    cudaGetSymbolAddress((void**)&imp,   g_imp);
    cudaGetSymbolAddress((void**)&tidx,  g_tidx);
    cudaGetSymbolAddress((void**)&xh,   g_xh);
    cudaGetSymbolAddress((void**)&qkvh, g_qkvh); cudaGetSymbolAddress((void**)&qkvl, g_qkvl);
    cudaGetSymbolAddress((void**)&qch,  g_qch);
    cudaGetSymbolAddress((void**)&qth,  g_qth);
    cudaGetSymbolAddress((void**)&aLh,  g_aLh);
    cudaGetSymbolAddress((void**)&aCh,  g_aCh);
    cudaGetSymbolAddress((void**)&aTh,  g_aTh);
    cudaGetSymbolAddress((void**)&ch,   g_ch);
    cudaGetSymbolAddress((void**)&sh,   g_sh);
    cudaGetSymbolAddress((void**)&kch,  g_kch);  cudaGetSymbolAddress((void**)&kcl,  g_kcl);
    cudaGetSymbolAddress((void**)&vch,  g_vch);
    cudaGetSymbolAddress((void**)&kth,  g_kth);  cudaGetSymbolAddress((void**)&ktl,  g_ktl);
    cudaGetSymbolAddress((void**)&vth,  g_vth);
    cudaGetSymbolAddress((void**)&wh,   g_wh);

    const int ATTN_SMEM = (128 + 3 * 64) * A3STR * 2 + 64 * 4;   // 46336
    cudaFuncSetAttribute(attn_mma, cudaFuncAttributeMaxDynamicSharedMemorySize, ATTN_SMEM);
    const int GEMM_SMEM = 2 * BUFSZ * 2;
    cudaFuncSetAttribute(mma_gemm, cudaFuncAttributeMaxDynamicSharedMemorySize, GEMM_SMEM);

    const int O_QKV = 0,    O_LO = 1536, O_CQ = 2048, O_CK = 2560, O_CV = 3072,
              O_CO = 3584,  O_GC = 4096, O_TQ = 4608, O_TK = 5120, O_TV = 5632,
              O_TO = 6144,  O_GT = 6656;
    #define WH(o) (wh + (size_t)(o) * 512)

    {
        WBatch wb;
        wb.s[0]  = {Wqkv, WH(O_QKV), 1536, 768};
        wb.s[1]  = {Wlo,  WH(O_LO),  512, 256};
        wb.s[2]  = {Wcq,  WH(O_CQ),  512, 256};
        wb.s[3]  = {Wck,  WH(O_CK),  512, 256};
        wb.s[4]  = {Wcv,  WH(O_CV),  512, 256};
        wb.s[5]  = {Wco,  WH(O_CO),  512, 256};
        wb.s[6]  = {Wgc,  WH(O_GC),  512, 256};
        wb.s[7]  = {Wtq,  WH(O_TQ),  512, 256};
        wb.s[8]  = {Wtk,  WH(O_TK),  512, 256};
        wb.s[9]  = {Wtv,  WH(O_TV),  512, 256};
        wb.s[10] = {Wto,  WH(O_TO),  512, 256};
        wb.s[11] = {Wgt,  WH(O_GT),  512, 256};
        wb.n = 12;
        conv_w<<<768 + 11 * 256, 256>>>(wb);
    }
    xprep_kernel<<<512, 512>>>(x, Wimp, bimp, xh, ch, imp);
    topk_gather<<<2, 256>>>(imp, x, tidx, sh);

    {
        MBatch mb;
        mb.s[0] = {xh, WH(O_QKV), bqkv, nullptr, qkvh, qkvl, 24, 32, 4, 1536};
        mb.s[1] = {xh, WH(O_CQ),  bcq,  nullptr, qch,  nullptr, 8, 32, 3, 512};
        mb.s[2] = {xh, WH(O_GC),  bgc,  gatec,  nullptr, nullptr, 8, 32, 1, 512};
        mb.s[3] = {xh, WH(O_TQ),  btq,  nullptr, qth,  nullptr, 8, 32, 3, 512};
        mb.s[4] = {xh, WH(O_GT),  bgt,  gatet,  nullptr, nullptr, 8, 32, 1, 512};
        mb.s[5] = {ch, WH(O_CK),  bck,  nullptr, kch,  kcl, 8, 3, 2, 512};
        mb.s[6] = {ch, WH(O_CV),  bcv,  nullptr, vch,  nullptr, 8, 3, 5, 512};
        mb.s[7] = {sh, WH(O_TK),  btk,  nullptr, kth,  ktl, 8, 1, 2, 512};
        mb.s[8] = {sh, WH(O_TV),  btv,  nullptr, vth,  nullptr, 8, 1, 5, 512};
        mb.n = 9;
        mma_gemm<<<1856, 256, GEMM_SMEM>>>(mb);
    }

    {
        AttnParams P;
        P.Qh[0] = qkvh;
        P.Kh[0] = qkvh + 512;  P.Kl[0] = qkvl + 512;
        P.Vh[0] = qkvh + 1024;
        P.Oh[0] = aLh; P.qs[0] = 1536; P.ks[0] = 1536; P.nk[0] = 2048;
        P.Qh[1] = qch; P.Kh[1] = kch; P.Kl[1] = kcl; P.Vh[1] = vch;
        P.Oh[1] = aCh; P.qs[1] = 512; P.ks[1] = 512; P.nk[1] = 192;
        P.Qh[2] = qth; P.Kh[2] = kth; P.Kl[2] = ktl; P.Vh[2] = vth;
        P.Oh[2] = aTh; P.qs[2] = 512; P.ks[2] = 512; P.nk[2] = 64;
        P.tidx = tidx;
        attn_mma<<<dim3(16, 8, 6), 256, ATTN_SMEM>>>(P);
    }

    float* buf0 = obuf;
    float* bufC = obuf + (size_t)NTOK * 512;
    float* bufT = obuf + (size_t)NTOK * 1024;
    {
        MBatch mb;
        mb.s[0] = {aLh, WH(O_LO), blo, buf0, nullptr, nullptr, 8, 32, 0, 512};
        mb.s[1] = {aCh, WH(O_CO), bco, bufC, nullptr, nullptr, 8, 32, 0, 512};
        mb.s[2] = {aTh, WH(O_TO), bto, bufT, nullptr, nullptr, 8, 32, 0, 512};
        mb.n = 3;
        mma_gemm<<<768, 256, GEMM_SMEM>>>(mb);
    }
    combine_kernel<<<NTOK * 512 / 1024, 256>>>(buf0, bufC, bufT, gatec, gatet, out);
}

// round 16
// speedup vs baseline: 1.1658x; 1.0045x over previous
#include <cuda_runtime.h>
#include <cuda_fp16.h>
#include <math.h>
#include <stdint.h>

#define S_LEN 2048
#define NTOK  4096
#define HDIM  64
#define NEGBIG -1e9f

// ===================== PTX helpers ==========================================
__device__ __forceinline__ void mma16816(float* c, const uint32_t* a,
                                         uint32_t b0, uint32_t b1) {
    asm volatile(
        "mma.sync.aligned.m16n8k16.row.col.f32.f16.f16.f32 "
        "{%0,%1,%2,%3}, {%4,%5,%6,%7}, {%8,%9}, {%0,%1,%2,%3};"
        : "+f"(c[0]), "+f"(c[1]), "+f"(c[2]), "+f"(c[3])
        : "r"(a[0]), "r"(a[1]), "r"(a[2]), "r"(a[3]), "r"(b0), "r"(b1));
}
__device__ __forceinline__ void ldsm_x4(uint32_t* r, uint32_t addr) {
    asm volatile("ldmatrix.sync.aligned.m8n8.x4.shared.b16 {%0,%1,%2,%3}, [%4];"
                 : "=r"(r[0]), "=r"(r[1]), "=r"(r[2]), "=r"(r[3]) : "r"(addr));
}
__device__ __forceinline__ void ldsm_x4_t(uint32_t* r, uint32_t addr) {
    asm volatile("ldmatrix.sync.aligned.m8n8.x4.trans.shared.b16 {%0,%1,%2,%3}, [%4];"
                 : "=r"(r[0]), "=r"(r[1]), "=r"(r[2]), "=r"(r[3]) : "r"(addr));
}
__device__ __forceinline__ uint32_t smem_u32(const void* p) {
    uint32_t a;
    asm("{ .reg .u64 t; cvta.to.shared.u64 t, %1; cvt.u32.u64 %0, t; }"
        : "=r"(a) : "l"(p));
    return a;
}
__device__ __forceinline__ void cp16(uint32_t dst, const void* src) {
    asm volatile("cp.async.cg.shared.global [%0], [%1], 16;" :: "r"(dst), "l"(src));
}
#define CP_COMMIT() asm volatile("cp.async.commit_group;" ::: "memory")
#define CP_WAIT0()  asm volatile("cp.async.wait_group 0;" ::: "memory")

// ===================== scratch ==============================================
__device__ __align__(16) float g_obuf [NTOK*1536];
__device__ __align__(16) float g_gatec[NTOK*512];
__device__ __align__(16) float g_gatet[NTOK*512];
__device__ __align__(16) float g_imp  [NTOK];
__device__ int   g_tidx [128];

__device__ __align__(16) __half g_xh[NTOK*512];
__device__ __align__(16) __half g_qkvh[NTOK*1536], g_qkvl[NTOK*1536];
__device__ __align__(16) __half g_qch[NTOK*512];
__device__ __align__(16) __half g_qth[NTOK*512];
__device__ __align__(16) __half g_aLh[NTOK*512];
__device__ __align__(16) __half g_aCh[NTOK*512];
__device__ __align__(16) __half g_aTh[NTOK*512];
__device__ __align__(16) __half g_ch[384*512];
__device__ __align__(16) __half g_sh[128*512];
__device__ __align__(16) __half g_kch[384*512], g_kcl[384*512];
__device__ __align__(16) __half g_vch[384*512];
__device__ __align__(16) __half g_kth[128*512], g_ktl[128*512];
__device__ __align__(16) __half g_vth[128*512];
__device__ __align__(16) __half g_wh[7168*512];

// ===================== merged prep: x-split/pool/imp + weight convert =======
// blocks [0,512): xprep;  blocks [512, 512+1792): conv_w 32k x 64n sub-tiles
struct WSeg { const float* W; __half* hi; int M; int blk; };
struct PrepArgs {
    const float* x; const float* Wimp; const float* bimp;
    __half* xh; __half* ch; float* imp;
    WSeg s[12]; int nseg;
};

__global__ __launch_bounds__(512) void prep_kernel(PrepArgs A)
{
    if (blockIdx.x < 512) {
        // ---- xprep ----
        __shared__ float wred[16][8];
        const int g = blockIdx.x;
        const int b = g >> 8, p = g & 255;
        const int d = threadIdx.x;
        const int lane = d & 31, wid = d >> 5;
        const float w = A.Wimp[d];

        float psum = 0.f, part[8];
#pragma unroll
        for (int r = 0; r < 8; r++) {
            size_t row = (size_t)(b * S_LEN + p * 8 + r);
            float v = A.x[row * 512 + d];
            A.xh[row * 512 + d] = __float2half(v);
            psum += v;
            part[r] = v * w;
        }
        if (p < 192) {
            size_t off = (size_t)(b * 192 + p) * 512 + d;
            A.ch[off] = __float2half(psum * 0.125f);
        }
#pragma unroll
        for (int r = 0; r < 8; r++) {
            float t = part[r];
#pragma unroll
            for (int off = 16; off; off >>= 1)
                t += __shfl_xor_sync(0xffffffffu, t, off);
            if (!lane) wred[wid][r] = t;
        }
        __syncthreads();
        if (d < 8) {
            float s = 0.f;
#pragma unroll
            for (int ww = 0; ww < 16; ww++) s += wred[ww][d];
            A.imp[b * S_LEN + p * 8 + d] = s + A.bimp[0];
        }
    } else {
        // ---- conv_w: 32 k-rows x 64 n-cols per block (two 32x32 halves) ----
        __shared__ float ts[2][32][33];
        int b = blockIdx.x - 512, si = 0;
        while (si < A.nseg - 1 && b >= A.s[si].blk) { b -= A.s[si].blk; si++; }
        const float* __restrict__ W = A.s[si].W;
        const int M = A.s[si].M;
        const int ntn = M >> 6;                       // 64-col tiles per row
        const int tk = (b / ntn) * 32, tn = (b % ntn) * 64;
        const int sub = threadIdx.x >> 8;             // 0/1: which 32-col half
        const int t8 = threadIdx.x & 255;
        const int tx = t8 & 31, ty = t8 >> 5;
#pragma unroll
        for (int i = 0; i < 4; i++)
            ts[sub][ty + 8 * i][tx] =
                W[(size_t)(tk + ty + 8 * i) * M + tn + sub * 32 + tx];
        __syncthreads();
#pragma unroll
        for (int i = 0; i < 4; i++) {
            int n = tn + sub * 32 + ty + 8 * i, k = tk + tx;
            A.s[si].hi[(size_t)n * 512 + k] = __float2half(ts[sub][tx][ty + 8 * i]);
        }
    }
}

// ===================== HMMA GEMM v10 (unchanged core, +gated epi 6) =========
struct MSeg {
    const __half *Ah, *Bh;
    const float* bias;
    float* C; __half *Ch, *Cl;
    const float* gate;
    int tx, ty, epi, Mout;
};
struct MBatch { MSeg s[9]; int n; };

#define SSTR  72
#define A_ARR (128 * SSTR)
#define B_ARR (64 * SSTR)
#define BUFSZ (A_ARR + B_ARR)

__global__ __launch_bounds__(256, 3) void mma_gemm(MBatch bt)
{
    extern __shared__ __half gsm[];

    int t = blockIdx.x, si = 0;
    while (si < bt.n - 1 && t >= bt.s[si].tx * bt.s[si].ty) {
        t -= bt.s[si].tx * bt.s[si].ty; si++;
    }
    const MSeg sg = bt.s[si];
    const int col0 = (t % sg.tx) * 64, row0 = (t / sg.tx) * 128;

    const int tid = threadIdx.x, wid = tid >> 5, lane = tid & 31;
    const int wr = wid & 3, wc = wid >> 2;
    const int lr = lane >> 2, lc = (lane & 3) * 2;

    float acc[2][4][4];
#pragma unroll
    for (int mt = 0; mt < 2; mt++)
#pragma unroll
        for (int nt = 0; nt < 4; nt++)
#pragma unroll
            for (int j = 0; j < 4; j++) acc[mt][nt][j] = 0.f;

    const int lrow = tid >> 3, lcol = (tid & 7) * 8;
    const __half* gA = sg.Ah + (size_t)(row0 + lrow) * 512 + lcol;
    const __half* gB = sg.Bh + (size_t)(col0 + lrow) * 512 + lcol;
    const uint32_t sA0 = smem_u32(gsm + lrow * SSTR + lcol);
    const uint32_t sB0 = sA0 + A_ARR * 2;

    auto load_chunk = [&](int d, int kc) {
        uint32_t dA = sA0 + d * (BUFSZ * 2);
        uint32_t dB = sB0 + d * (BUFSZ * 2);
#pragma unroll
        for (int i = 0; i < 4; i++)
            cp16(dA + i * (32 * SSTR * 2), gA + kc + i * (32 * 512));
#pragma unroll
        for (int i = 0; i < 2; i++)
            cp16(dB + i * (32 * SSTR * 2), gB + kc + i * (32 * 512));
        CP_COMMIT();
    };

    const int a_row = (lane & 7) + ((lane >> 3) & 1) * 8;
    const int a_col = (lane >> 4) * 8;
    const int b_row = (lane & 7) + ((lane >> 4) & 1) * 8;
    const int b_col = ((lane >> 3) & 1) * 8;

    const uint32_t aBase0 = smem_u32(gsm + (wr * 32 + a_row) * SSTR + a_col);
    const uint32_t bBase0 = smem_u32(gsm) + A_ARR * 2 +
                            ((wc * 32 + b_row) * SSTR + b_col) * 2;

    load_chunk(0, 0);

    for (int c = 0; c < 8; c++) {
        CP_WAIT0();
        __syncthreads();
        if (c + 1 < 8) load_chunk((c + 1) & 1, (c + 1) * 64);

        const uint32_t aBase = aBase0 + (c & 1) * (BUFSZ * 2);
        const uint32_t bBase = bBase0 + (c & 1) * (BUFSZ * 2);

#pragma unroll
        for (int ks = 0; ks < 4; ks++) {
            const int k0b = ks * 32;
            uint32_t af[2][4];
#pragma unroll
            for (int mt = 0; mt < 2; mt++)
                ldsm_x4(af[mt], aBase + mt * (16 * SSTR * 2) + k0b);
#pragma unroll
            for (int pr = 0; pr < 2; pr++) {
                uint32_t bh[4];
                ldsm_x4(bh, bBase + pr * (16 * SSTR * 2) + k0b);
#pragma unroll
                for (int half = 0; half < 2; half++) {
                    int nt = pr * 2 + half;
                    mma16816(acc[0][nt], af[0], bh[half * 2], bh[half * 2 + 1]);
                    mma16816(acc[1][nt], af[1], bh[half * 2], bh[half * 2 + 1]);
                }
            }
        }
    }

    const float* __restrict__ bias = sg.bias;
    const int Mout = sg.Mout, epi = sg.epi;
#pragma unroll
    for (int mt = 0; mt < 2; mt++) {
        int r = row0 + wr * 32 + mt * 16 + lr;
#pragma unroll
        for (int nt = 0; nt < 4; nt++) {
            int c = col0 + wc * 32 + nt * 8 + lc;
            float b0 = __ldg(bias + c), b1 = __ldg(bias + c + 1);
            float v0 = acc[mt][nt][0] + b0, v1 = acc[mt][nt][1] + b1;
            float v2 = acc[mt][nt][2] + b0, v3 = acc[mt][nt][3] + b1;
            size_t o0 = (size_t)r * Mout + c;
            size_t o1 = (size_t)(r + 8) * Mout + c;
            if (epi == 0) {
                *(float2*)(sg.C + o0) = make_float2(v0, v1);
                *(float2*)(sg.C + o1) = make_float2(v2, v3);
            } else if (epi == 6) {
                float2 g0 = *(const float2*)(sg.gate + o0);
                float2 g1 = *(const float2*)(sg.gate + o1);
                *(float2*)(sg.C + o0) = make_float2(g0.x * v0, g0.y * v1);
                *(float2*)(sg.C + o1) = make_float2(g1.x * v2, g1.y * v3);
            } else if (epi == 1) {
                *(float2*)(sg.C + o0) = make_float2(
                    1.f / (1.f + expf(-v0)), 1.f / (1.f + expf(-v1)));
                *(float2*)(sg.C + o1) = make_float2(
                    1.f / (1.f + expf(-v2)), 1.f / (1.f + expf(-v3)));
            } else if (epi == 3 || epi == 5) {
                if (epi == 3) { v0 *= 0.125f; v1 *= 0.125f; v2 *= 0.125f; v3 *= 0.125f; }
                *(__half2*)(sg.Ch + o0) = __halves2half2(__float2half(v0), __float2half(v1));
                *(__half2*)(sg.Ch + o1) = __halves2half2(__float2half(v2), __float2half(v3));
            } else {
                bool wlo = (epi == 2) || (c >= 512 && c < 1024);
                if (epi == 4 && c < 512) {
                    v0 *= 0.125f; v1 *= 0.125f; v2 *= 0.125f; v3 *= 0.125f;
                }
                __half h0 = __float2half(v0), h1 = __float2half(v1);
                __half h2 = __float2half(v2), h3 = __float2half(v3);
                *(__half2*)(sg.Ch + o0) = __halves2half2(h0, h1);
                *(__half2*)(sg.Ch + o1) = __halves2half2(h2, h3);
                if (wlo) {
                    *(__half2*)(sg.Cl + o0) = __halves2half2(
                        __float2half(v0 - __half2float(h0)),
                        __float2half(v1 - __half2float(h1)));
                    *(__half2*)(sg.Cl + o1) = __halves2half2(
                        __float2half(v2 - __half2float(h2)),
                        __float2half(v3 - __half2float(h3)));
                }
            }
        }
    }
}

// ===================== attention v3 (unchanged, passing) ====================
#define A3STR 72

struct AttnParams {
    const __half *Qh[3], *Kh[3], *Kl[3], *Vh[3];
    __half *Oh[3];
    int qs[3], ks[3], nk[3];
    const int* tidx;
};

__global__ __launch_bounds__(256, 2) void attn_mma(AttnParams P)
{
    extern __shared__ char dynsm[];
    __half* sQ  = (__half*)dynsm;
    __half* sKh = sQ  + 128 * A3STR;
    __half* sKl = sKh + 64 * A3STR;
    __half* sVh = sKl + 64 * A3STR;
    int*    pos = (int*)(sVh + 64 * A3STR);

    const int mode = blockIdx.z >> 1, b = blockIdx.z & 1;
    const int h = blockIdx.y, q0 = blockIdx.x * 128;
    const int tid = threadIdx.x, wid = tid >> 5, lane = tid & 31;
    const int lr = lane >> 2, lc = (lane & 3) * 2;
    const int r0 = wid * 16 + lr, r1 = r0 + 8;
    const int qq0 = q0 + r0, qq1 = q0 + r1;

    const int a_row = (lane & 7) + ((lane >> 3) & 1) * 8;
    const int a_col = (lane >> 4) * 8;
    const int b_row = (lane & 7) + ((lane >> 4) & 1) * 8;
    const int b_col = ((lane >> 3) & 1) * 8;
    const int v_row = (lane & 7) + ((lane >> 3) & 1) * 8;
    const int v_col = ((lane >> 4) & 1) * 8;

    const __half* Qh = P.Qh[mode];
    const __half* Kh = P.Kh[mode]; const __half* Kl = P.Kl[mode];
    const __half* Vh = P.Vh[mode];
    const int qs = P.qs[mode], ks = P.ks[mode], nk = P.nk[mode];

    {
        int r = tid >> 3, c8 = (tid & 7) * 8;
#pragma unroll
        for (int i = 0; i < 4; i++) {
            int row = r + i * 32;
            *(uint4*)(sQ + row * A3STR + c8) =
                *(const uint4*)(Qh + (size_t)(b * S_LEN + q0 + row) * qs + h * HDIM + c8);
        }
    }
    __syncthreads();

    uint32_t qf[4][4];
    {
        uint32_t qb = smem_u32(sQ + (wid * 16 + a_row) * A3STR + a_col);
#pragma unroll
        for (int kss = 0; kss < 4; kss++)
            ldsm_x4(qf[kss], qb + kss * 32);
    }

    float oacc[8][4];
#pragma unroll
    for (int nt = 0; nt < 8; nt++)
#pragma unroll
        for (int j = 0; j < 4; j++) oacc[nt][j] = 0.f;

    float m0 = -INFINITY, m1 = -INFINITY, l0 = 0.f, l1 = 0.f;

    int kt0 = 0, ktend = nk;
    if (mode == 0) { kt0 = (q0 > 511) ? ((q0 - 511) & ~63) : 0; ktend = q0 + 128; }

    const int klr = tid >> 3, klc = (tid & 7) * 8;

    for (int kt = kt0; kt < ktend; kt += 64) {
        __syncthreads();
        {
            size_t gb = (size_t)(b * nk + kt + klr) * ks + h * HDIM + klc;
            size_t step = (size_t)32 * ks;
#pragma unroll
            for (int i = 0; i < 2; i++) {
                *(uint4*)(sKh + (klr + i * 32) * A3STR + klc) = *(const uint4*)(Kh + gb + i * step);
                *(uint4*)(sKl + (klr + i * 32) * A3STR + klc) = *(const uint4*)(Kl + gb + i * step);
                *(uint4*)(sVh + (klr + i * 32) * A3STR + klc) = *(const uint4*)(Vh + gb + i * step);
            }
        }
        if (tid < 64) {
            int j = kt + tid;
            pos[tid] = (mode == 0) ? j : (mode == 1 ? (j + 1) * 8 : P.tidx[b * 64 + j]);
        }
        __syncthreads();

        float sacc[8][4];
#pragma unroll
        for (int nt = 0; nt < 8; nt++)
#pragma unroll
            for (int j = 0; j < 4; j++) sacc[nt][j] = 0.f;

        const uint32_t khb = smem_u32(sKh + b_row * A3STR + b_col);
        const uint32_t klb = smem_u32(sKl + b_row * A3STR + b_col);
#pragma unroll
        for (int kss = 0; kss < 4; kss++) {
            const int k0b = kss * 32;
#pragma unroll
            for (int pr = 0; pr < 4; pr++) {
                uint32_t kh[4];
                ldsm_x4(kh, khb + pr * (16 * A3STR * 2) + k0b);
                mma16816(sacc[2 * pr],     qf[kss], kh[0], kh[1]);
                mma16816(sacc[2 * pr + 1], qf[kss], kh[2], kh[3]);
            }
#pragma unroll
            for (int pr = 0; pr < 4; pr++) {
                uint32_t kl[4];
                ldsm_x4(kl, klb + pr * (16 * A3STR * 2) + k0b);
                mma16816(sacc[2 * pr],     qf[kss], kl[0], kl[1]);
                mma16816(sacc[2 * pr + 1], qf[kss], kl[2], kl[3]);
            }
        }

        float bx0 = -INFINITY, bx1 = -INFINITY;
#pragma unroll
        for (int nt = 0; nt < 8; nt++) {
#pragma unroll
            for (int ci = 0; ci < 2; ci++) {
                int p = pos[nt * 8 + lc + ci];
                bool v0 = (mode == 0) ? ((unsigned)(qq0 - p) < 512u) : (qq0 >= p);
                bool v1 = (mode == 0) ? ((unsigned)(qq1 - p) < 512u) : (qq1 >= p);
                if (!v0) sacc[nt][ci] = NEGBIG;
                if (!v1) sacc[nt][2 + ci] = NEGBIG;
                bx0 = fmaxf(bx0, sacc[nt][ci]);
                bx1 = fmaxf(bx1, sacc[nt][2 + ci]);
            }
        }
        bx0 = fmaxf(bx0, __shfl_xor_sync(0xffffffffu, bx0, 1));
        bx0 = fmaxf(bx0, __shfl_xor_sync(0xffffffffu, bx0, 2));
        bx1 = fmaxf(bx1, __shfl_xor_sync(0xffffffffu, bx1, 1));
        bx1 = fmaxf(bx1, __shfl_xor_sync(0xffffffffu, bx1, 2));
        float mn0 = fmaxf(m0, bx0), mn1 = fmaxf(m1, bx1);

        uint32_t pr0[8], pr1[8];
        float lt0 = 0.f, lt1 = 0.f;
#pragma unroll
        for (int nt = 0; nt < 8; nt++) {
            float e0 = expf(sacc[nt][0] - mn0), e1 = expf(sacc[nt][1] - mn0);
            float e2 = expf(sacc[nt][2] - mn1), e3 = expf(sacc[nt][3] - mn1);
            lt0 += e0 + e1; lt1 += e2 + e3;
            __half2 hp0 = __halves2half2(__float2half(e0), __float2half(e1));
            __half2 hp1 = __halves2half2(__float2half(e2), __float2half(e3));
            pr0[nt] = *(uint32_t*)&hp0;
            pr1[nt] = *(uint32_t*)&hp1;
        }
        lt0 += __shfl_xor_sync(0xffffffffu, lt0, 1);
        lt0 += __shfl_xor_sync(0xffffffffu, lt0, 2);
        lt1 += __shfl_xor_sync(0xffffffffu, lt1, 1);
        lt1 += __shfl_xor_sync(0xffffffffu, lt1, 2);

        float al0 = expf(m0 - mn0), al1 = expf(m1 - mn1);
        m0 = mn0; m1 = mn1;
        l0 = l0 * al0 + lt0;
        l1 = l1 * al1 + lt1;
#pragma unroll
        for (int nt = 0; nt < 8; nt++) {
            oacc[nt][0] *= al0; oacc[nt][1] *= al0;
            oacc[nt][2] *= al1; oacc[nt][3] *= al1;
        }

        const uint32_t vb = smem_u32(sVh + v_row * A3STR + v_col);
#pragma unroll
        for (int kb = 0; kb < 4; kb++) {
            uint32_t af[4] = { pr0[2 * kb], pr1[2 * kb], pr0[2 * kb + 1], pr1[2 * kb + 1] };
#pragma unroll
            for (int vt = 0; vt < 4; vt++) {
                uint32_t vh[4];
                ldsm_x4_t(vh, vb + kb * (16 * A3STR * 2) + vt * 32);
                mma16816(oacc[2 * vt],     af, vh[0], vh[1]);
                mma16816(oacc[2 * vt + 1], af, vh[2], vh[3]);
            }
        }
    }

    float i0 = 1.f / l0, i1 = 1.f / l1;
    __half* Oh = P.Oh[mode];
#pragma unroll
    for (int nt = 0; nt < 8; nt++) {
        int c = h * HDIM + nt * 8 + lc;
        size_t o0 = (size_t)(b * S_LEN + qq0) * 512 + c;
        size_t o1 = (size_t)(b * S_LEN + qq1) * 512 + c;
        *(__half2*)(Oh + o0) = __halves2half2(
            __float2half(oacc[nt][0] * i0), __float2half(oacc[nt][1] * i0));
        *(__half2*)(Oh + o1) = __halves2half2(
            __float2half(oacc[nt][2] * i1), __float2half(oacc[nt][3] * i1));
    }
}

// ===================== fused topk + gather ==================================
__global__ __launch_bounds__(256) void topk_gather(
    const float* __restrict__ imp, const float* __restrict__ x,
    int* __restrict__ tidx, __half* __restrict__ sh)
{
    int b = blockIdx.x;
    __shared__ float v[2048];
    __shared__ float wv[8];
    __shared__ int   wi[8];
    __shared__ int   sel[64];
    const int tid = threadIdx.x, lane = tid & 31, wid = tid >> 5;

    for (int i = tid; i < 2048; i += 256) v[i] = imp[b * 2048 + i];
    __syncthreads();

    for (int r = 0; r < 64; r++) {
        float bv = -INFINITY; int bi = 0x7fffffff;
        for (int i = tid; i < 2048; i += 256) {
            float xv = v[i];
            if (xv > bv) { bv = xv; bi = i; }
        }
#pragma unroll
        for (int off = 16; off; off >>= 1) {
            float ov = __shfl_xor_sync(0xffffffffu, bv, off);
            int   oi = __shfl_xor_sync(0xffffffffu, bi, off);
            if (ov > bv || (ov == bv && oi < bi)) { bv = ov; bi = oi; }
        }
        if (!lane) { wv[wid] = bv; wi[wid] = bi; }
        __syncthreads();
        if (wid == 0) {
            float cv = (lane < 8) ? wv[lane] : -INFINITY;
            int   ci = (lane < 8) ? wi[lane] : 0x7fffffff;
#pragma unroll
            for (int off = 4; off; off >>= 1) {
                float ov = __shfl_xor_sync(0xffffffffu, cv, off);
                int   oi = __shfl_xor_sync(0xffffffffu, ci, off);
                if (ov > cv || (ov == cv && oi < ci)) { cv = ov; ci = oi; }
            }
            if (!lane) { sel[r] = ci; tidx[b * 64 + r] = ci; v[ci] = -INFINITY; }
        }
        __syncthreads();
    }

    for (int r = 0; r < 64; r++) {
        int src = sel[r];
        for (int d = tid; d < 512; d += 256)
            sh[(size_t)(b * 64 + r) * 512 + d] =
                __float2half(x[(size_t)(b * S_LEN + src) * 512 + d]);
    }
}

__global__ void combine_kernel(const float* __restrict__ b0, const float* __restrict__ bC,
                               const float* __restrict__ bT, float* __restrict__ out)
{
    int i = (blockIdx.x * 256 + threadIdx.x) * 4;
    float4 v0 = *(const float4*)(b0 + i);
    float4 vC = *(const float4*)(bC + i);
    float4 vT = *(const float4*)(bT + i);
    v0.x += vC.x + vT.x;
    v0.y += vC.y + vT.y;
    v0.z += vC.z + vT.z;
    v0.w += vC.w + vT.w;
    *(float4*)(out + i) = v0;
}

// ===================== launch ===============================================
extern "C" void kernel_launch(void* const* d_in, const int* in_sizes, int n_in,
                              void* d_out, int out_size)
{
    const float* x    = (const float*)d_in[0];
    const float* Wqkv = (const float*)d_in[1];  const float* bqkv = (const float*)d_in[2];
    const float* Wlo  = (const float*)d_in[3];  const float* blo  = (const float*)d_in[4];
    const float* Wcq  = (const float*)d_in[5];  const float* bcq  = (const float*)d_in[6];
    const float* Wck  = (const float*)d_in[7];  const float* bck  = (const float*)d_in[8];
    const float* Wcv  = (const float*)d_in[9];  const float* bcv  = (const float*)d_in[10];
    const float* Wco  = (const float*)d_in[11]; const float* bco  = (const float*)d_in[12];
    const float* Wgc  = (const float*)d_in[13]; const float* bgc  = (const float*)d_in[14];
    const float* Wimp = (const float*)d_in[15]; const float* bimp = (const float*)d_in[16];
    const float* Wtq  = (const float*)d_in[17]; const float* btq  = (const float*)d_in[18];
    const float* Wtk  = (const float*)d_in[19]; const float* btk  = (const float*)d_in[20];
    const float* Wtv  = (const float*)d_in[21]; const float* btv  = (const float*)d_in[22];
    const float* Wto  = (const float*)d_in[23]; const float* bto  = (const float*)d_in[24];
    const float* Wgt  = (const float*)d_in[25]; const float* bgt  = (const float*)d_in[26];
    float* out = (float*)d_out;

    float *obuf, *gatec, *gatet, *imp;
    int* tidx;
    __half *xh, *qkvh, *qkvl, *qch, *qth, *aLh, *aCh, *aTh;
    __half *ch, *sh, *kch, *kcl, *vch, *kth, *ktl, *vth, *wh;
    cudaGetSymbolAddress((void**)&obuf,  g_obuf);
    cudaGetSymbolAddress((void**)&gatec, g_gatec);
    cudaGetSymbolAddress((void**)&gatet, g_gatet);
    cudaGetSymbolAddress((void**)&imp,   g_imp);
    cudaGetSymbolAddress((void**)&tidx,  g_tidx);
    cudaGetSymbolAddress((void**)&xh,   g_xh);
    cudaGetSymbolAddress((void**)&qkvh, g_qkvh); cudaGetSymbolAddress((void**)&qkvl, g_qkvl);
    cudaGetSymbolAddress((void**)&qch,  g_qch);
    cudaGetSymbolAddress((void**)&qth,  g_qth);
    cudaGetSymbolAddress((void**)&aLh,  g_aLh);
    cudaGetSymbolAddress((void**)&aCh,  g_aCh);
    cudaGetSymbolAddress((void**)&aTh,  g_aTh);
    cudaGetSymbolAddress((void**)&ch,   g_ch);
    cudaGetSymbolAddress((void**)&sh,   g_sh);
    cudaGetSymbolAddress((void**)&kch,  g_kch);  cudaGetSymbolAddress((void**)&kcl,  g_kcl);
    cudaGetSymbolAddress((void**)&vch,  g_vch);
    cudaGetSymbolAddress((void**)&kth,  g_kth);  cudaGetSymbolAddress((void**)&ktl,  g_ktl);
    cudaGetSymbolAddress((void**)&vth,  g_vth);
    cudaGetSymbolAddress((void**)&wh,   g_wh);

    const int ATTN_SMEM = (128 + 3 * 64) * A3STR * 2 + 64 * 4;
    cudaFuncSetAttribute(attn_mma, cudaFuncAttributeMaxDynamicSharedMemorySize, ATTN_SMEM);
    const int GEMM_SMEM = 2 * BUFSZ * 2;
    cudaFuncSetAttribute(mma_gemm, cudaFuncAttributeMaxDynamicSharedMemorySize, GEMM_SMEM);

    const int O_QKV = 0,    O_LO = 1536, O_CQ = 2048, O_CK = 2560, O_CV = 3072,
              O_CO = 3584,  O_GC = 4096, O_TQ = 4608, O_TK = 5120, O_TV = 5632,
              O_TO = 6144,  O_GT = 6656;
    #define WH(o) (wh + (size_t)(o) * 512)

    // 0) merged prep: xprep (512 blocks) + weight convert (1792 blocks)
    {
        PrepArgs A;
        A.x = x; A.Wimp = Wimp; A.bimp = bimp;
        A.xh = xh; A.ch = ch; A.imp = imp;
        A.s[0]  = {Wqkv, WH(O_QKV), 1536, 384};
        A.s[1]  = {Wlo,  WH(O_LO),  512, 128};
        A.s[2]  = {Wcq,  WH(O_CQ),  512, 128};
        A.s[3]  = {Wck,  WH(O_CK),  512, 128};
        A.s[4]  = {Wcv,  WH(O_CV),  512, 128};
        A.s[5]  = {Wco,  WH(O_CO),  512, 128};
        A.s[6]  = {Wgc,  WH(O_GC),  512, 128};
        A.s[7]  = {Wtq,  WH(O_TQ),  512, 128};
        A.s[8]  = {Wtk,  WH(O_TK),  512, 128};
        A.s[9]  = {Wtv,  WH(O_TV),  512, 128};
        A.s[10] = {Wto,  WH(O_TO),  512, 128};
        A.s[11] = {Wgt,  WH(O_GT),  512, 128};
        A.nseg = 12;
        prep_kernel<<<512 + 384 + 11 * 128, 512>>>(A);
    }
    topk_gather<<<2, 256>>>(imp, x, tidx, sh);

    // 1) mega GEMM
    {
        MBatch mb;
        mb.s[0] = {xh, WH(O_QKV), bqkv, nullptr, qkvh, qkvl, nullptr, 24, 32, 4, 1536};
        mb.s[1] = {xh, WH(O_CQ),  bcq,  nullptr, qch,  nullptr, nullptr, 8, 32, 3, 512};
        mb.s[2] = {xh, WH(O_GC),  bgc,  gatec,  nullptr, nullptr, nullptr, 8, 32, 1, 512};
        mb.s[3] = {xh, WH(O_TQ),  btq,  nullptr, qth,  nullptr, nullptr, 8, 32, 3, 512};
        mb.s[4] = {xh, WH(O_GT),  bgt,  gatet,  nullptr, nullptr, nullptr, 8, 32, 1, 512};
        mb.s[5] = {ch, WH(O_CK),  bck,  nullptr, kch,  kcl, nullptr, 8, 3, 2, 512};
        mb.s[6] = {ch, WH(O_CV),  bcv,  nullptr, vch,  nullptr, nullptr, 8, 3, 5, 512};
        mb.s[7] = {sh, WH(O_TK),  btk,  nullptr, kth,  ktl, nullptr, 8, 1, 2, 512};
        mb.s[8] = {sh, WH(O_TV),  btv,  nullptr, vth,  nullptr, nullptr, 8, 1, 5, 512};
        mb.n = 9;
        mma_gemm<<<1856, 256, GEMM_SMEM>>>(mb);
    }

    // 2) attentions
    {
        AttnParams P;
        P.Qh[0] = qkvh;
        P.Kh[0] = qkvh + 512;  P.Kl[0] = qkvl + 512;
        P.Vh[0] = qkvh + 1024;
        P.Oh[0] = aLh; P.qs[0] = 1536; P.ks[0] = 1536; P.nk[0] = 2048;
        P.Qh[1] = qch; P.Kh[1] = kch; P.Kl[1] = kcl; P.Vh[1] = vch;
        P.Oh[1] = aCh; P.qs[1] = 512; P.ks[1] = 512; P.nk[1] = 192;
        P.Qh[2] = qth; P.Kh[2] = kth; P.Kl[2] = ktl; P.Vh[2] = vth;
        P.Oh[2] = aTh; P.qs[2] = 512; P.ks[2] = 512; P.nk[2] = 64;
        P.tidx = tidx;
        attn_mma<<<dim3(16, 8, 6), 256, ATTN_SMEM>>>(P);
    }

    // 3) output projections (gated epilogues for C/T) + 3-way combine
    float* buf0 = obuf;
    float* bufC = obuf + (size_t)NTOK * 512;
    float* bufT = obuf + (size_t)NTOK * 1024;
    {
        MBatch mb;
        mb.s[0] = {aLh, WH(O_LO), blo, buf0, nullptr, nullptr, nullptr, 8, 32, 0, 512};
        mb.s[1] = {aCh, WH(O_CO), bco, bufC, nullptr, nullptr, gatec,  8, 32, 6, 512};
        mb.s[2] = {aTh, WH(O_TO), bto, bufT, nullptr, nullptr, gatet,  8, 32, 6, 512};
        mb.n = 3;
        mma_gemm<<<768, 256, GEMM_SMEM>>>(mb);
    }
    combine_kernel<<<NTOK * 512 / 1024, 256>>>(buf0, bufC, bufT, out);
}

// round 17
// speedup vs baseline: 1.1816x; 1.0135x over previous
#include <cuda_runtime.h>
#include <cuda_fp16.h>
#include <math.h>
#include <stdint.h>

#define S_LEN 2048
#define NTOK  4096
#define HDIM  64
#define NEGBIG -1e9f

// ===================== PTX helpers ==========================================
__device__ __forceinline__ void mma16816(float* c, const uint32_t* a,
                                         uint32_t b0, uint32_t b1) {
    asm volatile(
        "mma.sync.aligned.m16n8k16.row.col.f32.f16.f16.f32 "
        "{%0,%1,%2,%3}, {%4,%5,%6,%7}, {%8,%9}, {%0,%1,%2,%3};"
        : "+f"(c[0]), "+f"(c[1]), "+f"(c[2]), "+f"(c[3])
        : "r"(a[0]), "r"(a[1]), "r"(a[2]), "r"(a[3]), "r"(b0), "r"(b1));
}
__device__ __forceinline__ void ldsm_x4(uint32_t* r, uint32_t addr) {
    asm volatile("ldmatrix.sync.aligned.m8n8.x4.shared.b16 {%0,%1,%2,%3}, [%4];"
                 : "=r"(r[0]), "=r"(r[1]), "=r"(r[2]), "=r"(r[3]) : "r"(addr));
}
__device__ __forceinline__ void ldsm_x4_t(uint32_t* r, uint32_t addr) {
    asm volatile("ldmatrix.sync.aligned.m8n8.x4.trans.shared.b16 {%0,%1,%2,%3}, [%4];"
                 : "=r"(r[0]), "=r"(r[1]), "=r"(r[2]), "=r"(r[3]) : "r"(addr));
}
__device__ __forceinline__ uint32_t smem_u32(const void* p) {
    uint32_t a;
    asm("{ .reg .u64 t; cvta.to.shared.u64 t, %1; cvt.u32.u64 %0, t; }"
        : "=r"(a) : "l"(p));
    return a;
}
__device__ __forceinline__ void cp16(uint32_t dst, const void* src) {
    asm volatile("cp.async.cg.shared.global [%0], [%1], 16;" :: "r"(dst), "l"(src));
}
#define CP_COMMIT() asm volatile("cp.async.commit_group;" ::: "memory")
#define CP_WAIT0()  asm volatile("cp.async.wait_group 0;" ::: "memory")

// ===================== scratch ==============================================
__device__ __align__(16) float g_obuf [NTOK*1536];
__device__ __align__(16) float g_gatec[NTOK*512];
__device__ __align__(16) float g_gatet[NTOK*512];
__device__ __align__(16) float g_imp  [NTOK];
__device__ int   g_tidx [128];

__device__ __align__(16) __half g_xh[NTOK*512];
__device__ __align__(16) __half g_qkvh[NTOK*1536], g_qkvl[NTOK*1536];
__device__ __align__(16) __half g_qch[NTOK*512];
__device__ __align__(16) __half g_qth[NTOK*512];
__device__ __align__(16) __half g_aLh[NTOK*512];
__device__ __align__(16) __half g_aCh[NTOK*512];
__device__ __align__(16) __half g_aTh[NTOK*512];
__device__ __align__(16) __half g_ch[384*512];
__device__ __align__(16) __half g_sh[128*512];
__device__ __align__(16) __half g_kch[384*512], g_kcl[384*512];
__device__ __align__(16) __half g_vch[384*512];
__device__ __align__(16) __half g_kth[128*512], g_ktl[128*512];
__device__ __align__(16) __half g_vth[128*512];
__device__ __align__(16) __half g_wh[7168*512];

// ===================== merged prep: x-split/pool/imp + weight convert =======
struct WSeg { const float* W; __half* hi; int M; int blk; };
struct PrepArgs {
    const float* x; const float* Wimp; const float* bimp;
    __half* xh; __half* ch; float* imp;
    WSeg s[12]; int nseg;
};

__global__ __launch_bounds__(512) void prep_kernel(PrepArgs A)
{
    if (blockIdx.x < 512) {
        __shared__ float wred[16][8];
        const int g = blockIdx.x;
        const int b = g >> 8, p = g & 255;
        const int d = threadIdx.x;
        const int lane = d & 31, wid = d >> 5;
        const float w = A.Wimp[d];

        float psum = 0.f, part[8];
#pragma unroll
        for (int r = 0; r < 8; r++) {
            size_t row = (size_t)(b * S_LEN + p * 8 + r);
            float v = A.x[row * 512 + d];
            A.xh[row * 512 + d] = __float2half(v);
            psum += v;
            part[r] = v * w;
        }
        if (p < 192) {
            size_t off = (size_t)(b * 192 + p) * 512 + d;
            A.ch[off] = __float2half(psum * 0.125f);
        }
#pragma unroll
        for (int r = 0; r < 8; r++) {
            float t = part[r];
#pragma unroll
            for (int off = 16; off; off >>= 1)
                t += __shfl_xor_sync(0xffffffffu, t, off);
            if (!lane) wred[wid][r] = t;
        }
        __syncthreads();
        if (d < 8) {
            float s = 0.f;
#pragma unroll
            for (int ww = 0; ww < 16; ww++) s += wred[ww][d];
            A.imp[b * S_LEN + p * 8 + d] = s + A.bimp[0];
        }
    } else {
        __shared__ float ts[2][32][33];
        int b = blockIdx.x - 512, si = 0;
        while (si < A.nseg - 1 && b >= A.s[si].blk) { b -= A.s[si].blk; si++; }
        const float* __restrict__ W = A.s[si].W;
        const int M = A.s[si].M;
        const int ntn = M >> 6;
        const int tk = (b / ntn) * 32, tn = (b % ntn) * 64;
        const int sub = threadIdx.x >> 8;
        const int t8 = threadIdx.x & 255;
        const int tx = t8 & 31, ty = t8 >> 5;
#pragma unroll
        for (int i = 0; i < 4; i++)
            ts[sub][ty + 8 * i][tx] =
                W[(size_t)(tk + ty + 8 * i) * M + tn + sub * 32 + tx];
        __syncthreads();
#pragma unroll
        for (int i = 0; i < 4; i++) {
            int n = tn + sub * 32 + ty + 8 * i, k = tk + tx;
            A.s[si].hi[(size_t)n * 512 + k] = __float2half(ts[sub][tx][ty + 8 * i]);
        }
    }
}

// ===================== HMMA GEMM v10 (unchanged core) =======================
struct MSeg {
    const __half *Ah, *Bh;
    const float* bias;
    float* C; __half *Ch, *Cl;
    const float* gate;
    int tx, ty, epi, Mout;
};
struct MBatch { MSeg s[9]; int n; };

#define SSTR  72
#define A_ARR (128 * SSTR)
#define B_ARR (64 * SSTR)
#define BUFSZ (A_ARR + B_ARR)

__global__ __launch_bounds__(256, 3) void mma_gemm(MBatch bt)
{
    extern __shared__ __half gsm[];

    int t = blockIdx.x, si = 0;
    while (si < bt.n - 1 && t >= bt.s[si].tx * bt.s[si].ty) {
        t -= bt.s[si].tx * bt.s[si].ty; si++;
    }
    const MSeg sg = bt.s[si];
    const int col0 = (t % sg.tx) * 64, row0 = (t / sg.tx) * 128;

    const int tid = threadIdx.x, wid = tid >> 5, lane = tid & 31;
    const int wr = wid & 3, wc = wid >> 2;
    const int lr = lane >> 2, lc = (lane & 3) * 2;

    float acc[2][4][4];
#pragma unroll
    for (int mt = 0; mt < 2; mt++)
#pragma unroll
        for (int nt = 0; nt < 4; nt++)
#pragma unroll
            for (int j = 0; j < 4; j++) acc[mt][nt][j] = 0.f;

    const int lrow = tid >> 3, lcol = (tid & 7) * 8;
    const __half* gA = sg.Ah + (size_t)(row0 + lrow) * 512 + lcol;
    const __half* gB = sg.Bh + (size_t)(col0 + lrow) * 512 + lcol;
    const uint32_t sA0 = smem_u32(gsm + lrow * SSTR + lcol);
    const uint32_t sB0 = sA0 + A_ARR * 2;

    auto load_chunk = [&](int d, int kc) {
        uint32_t dA = sA0 + d * (BUFSZ * 2);
        uint32_t dB = sB0 + d * (BUFSZ * 2);
#pragma unroll
        for (int i = 0; i < 4; i++)
            cp16(dA + i * (32 * SSTR * 2), gA + kc + i * (32 * 512));
#pragma unroll
        for (int i = 0; i < 2; i++)
            cp16(dB + i * (32 * SSTR * 2), gB + kc + i * (32 * 512));
        CP_COMMIT();
    };

    const int a_row = (lane & 7) + ((lane >> 3) & 1) * 8;
    const int a_col = (lane >> 4) * 8;
    const int b_row = (lane & 7) + ((lane >> 4) & 1) * 8;
    const int b_col = ((lane >> 3) & 1) * 8;

    const uint32_t aBase0 = smem_u32(gsm + (wr * 32 + a_row) * SSTR + a_col);
    const uint32_t bBase0 = smem_u32(gsm) + A_ARR * 2 +
                            ((wc * 32 + b_row) * SSTR + b_col) * 2;

    load_chunk(0, 0);

    for (int c = 0; c < 8; c++) {
        CP_WAIT0();
        __syncthreads();
        if (c + 1 < 8) load_chunk((c + 1) & 1, (c + 1) * 64);

        const uint32_t aBase = aBase0 + (c & 1) * (BUFSZ * 2);
        const uint32_t bBase = bBase0 + (c & 1) * (BUFSZ * 2);

#pragma unroll
        for (int ks = 0; ks < 4; ks++) {
            const int k0b = ks * 32;
            uint32_t af[2][4];
#pragma unroll
            for (int mt = 0; mt < 2; mt++)
                ldsm_x4(af[mt], aBase + mt * (16 * SSTR * 2) + k0b);
#pragma unroll
            for (int pr = 0; pr < 2; pr++) {
                uint32_t bh[4];
                ldsm_x4(bh, bBase + pr * (16 * SSTR * 2) + k0b);
#pragma unroll
                for (int half = 0; half < 2; half++) {
                    int nt = pr * 2 + half;
                    mma16816(acc[0][nt], af[0], bh[half * 2], bh[half * 2 + 1]);
                    mma16816(acc[1][nt], af[1], bh[half * 2], bh[half * 2 + 1]);
                }
            }
        }
    }

    const float* __restrict__ bias = sg.bias;
    const int Mout = sg.Mout, epi = sg.epi;
#pragma unroll
    for (int mt = 0; mt < 2; mt++) {
        int r = row0 + wr * 32 + mt * 16 + lr;
#pragma unroll
        for (int nt = 0; nt < 4; nt++) {
            int c = col0 + wc * 32 + nt * 8 + lc;
            float b0 = __ldg(bias + c), b1 = __ldg(bias + c + 1);
            float v0 = acc[mt][nt][0] + b0, v1 = acc[mt][nt][1] + b1;
            float v2 = acc[mt][nt][2] + b0, v3 = acc[mt][nt][3] + b1;
            size_t o0 = (size_t)r * Mout + c;
            size_t o1 = (size_t)(r + 8) * Mout + c;
            if (epi == 0) {
                *(float2*)(sg.C + o0) = make_float2(v0, v1);
                *(float2*)(sg.C + o1) = make_float2(v2, v3);
            } else if (epi == 6) {
                float2 g0 = *(const float2*)(sg.gate + o0);
                float2 g1 = *(const float2*)(sg.gate + o1);
                *(float2*)(sg.C + o0) = make_float2(g0.x * v0, g0.y * v1);
                *(float2*)(sg.C + o1) = make_float2(g1.x * v2, g1.y * v3);
            } else if (epi == 1) {
                *(float2*)(sg.C + o0) = make_float2(
                    1.f / (1.f + __expf(-v0)), 1.f / (1.f + __expf(-v1)));
                *(float2*)(sg.C + o1) = make_float2(
                    1.f / (1.f + __expf(-v2)), 1.f / (1.f + __expf(-v3)));
            } else if (epi == 3 || epi == 5) {
                if (epi == 3) { v0 *= 0.125f; v1 *= 0.125f; v2 *= 0.125f; v3 *= 0.125f; }
                *(__half2*)(sg.Ch + o0) = __halves2half2(__float2half(v0), __float2half(v1));
                *(__half2*)(sg.Ch + o1) = __halves2half2(__float2half(v2), __float2half(v3));
            } else {
                bool wlo = (epi == 2) || (c >= 512 && c < 1024);
                if (epi == 4 && c < 512) {
                    v0 *= 0.125f; v1 *= 0.125f; v2 *= 0.125f; v3 *= 0.125f;
                }
                __half h0 = __float2half(v0), h1 = __float2half(v1);
                __half h2 = __float2half(v2), h3 = __float2half(v3);
                *(__half2*)(sg.Ch + o0) = __halves2half2(h0, h1);
                *(__half2*)(sg.Ch + o1) = __halves2half2(h2, h3);
                if (wlo) {
                    *(__half2*)(sg.Cl + o0) = __halves2half2(
                        __float2half(v0 - __half2float(h0)),
                        __float2half(v1 - __half2float(h1)));
                    *(__half2*)(sg.Cl + o1) = __halves2half2(
                        __float2half(v2 - __half2float(h2)),
                        __float2half(v3 - __half2float(h3)));
                }
            }
        }
    }
}

// ===================== attention v4: fast-exp, arithmetic masks =============
#define A3STR 72

struct AttnParams {
    const __half *Qh[3], *Kh[3], *Kl[3], *Vh[3];
    __half *Oh[3];
    int qs[3], ks[3], nk[3];
    const int* tidx;
};

__global__ __launch_bounds__(256, 2) void attn_mma(AttnParams P)
{
    extern __shared__ char dynsm[];
    __half* sQ  = (__half*)dynsm;
    __half* sKh = sQ  + 128 * A3STR;
    __half* sKl = sKh + 64 * A3STR;
    __half* sVh = sKl + 64 * A3STR;
    int*    pos = (int*)(sVh + 64 * A3STR);

    const int mode = blockIdx.z >> 1, b = blockIdx.z & 1;
    const int h = blockIdx.y, q0 = blockIdx.x * 128;
    const int tid = threadIdx.x, wid = tid >> 5, lane = tid & 31;
    const int lr = lane >> 2, lc = (lane & 3) * 2;
    const int r0 = wid * 16 + lr, r1 = r0 + 8;
    const int qq0 = q0 + r0, qq1 = q0 + r1;

    const int a_row = (lane & 7) + ((lane >> 3) & 1) * 8;
    const int a_col = (lane >> 4) * 8;
    const int b_row = (lane & 7) + ((lane >> 4) & 1) * 8;
    const int b_col = ((lane >> 3) & 1) * 8;
    const int v_row = (lane & 7) + ((lane >> 3) & 1) * 8;
    const int v_col = ((lane >> 4) & 1) * 8;

    const __half* Qh = P.Qh[mode];
    const __half* Kh = P.Kh[mode]; const __half* Kl = P.Kl[mode];
    const __half* Vh = P.Vh[mode];
    const int qs = P.qs[mode], ks = P.ks[mode], nk = P.nk[mode];

    {
        int r = tid >> 3, c8 = (tid & 7) * 8;
#pragma unroll
        for (int i = 0; i < 4; i++) {
            int row = r + i * 32;
            *(uint4*)(sQ + row * A3STR + c8) =
                *(const uint4*)(Qh + (size_t)(b * S_LEN + q0 + row) * qs + h * HDIM + c8);
        }
    }
    // mode 2: topk positions loaded once (single k-tile)
    if (mode == 2 && tid < 64) pos[tid] = P.tidx[b * 64 + tid];
    __syncthreads();

    uint32_t qf[4][4];
    {
        uint32_t qb = smem_u32(sQ + (wid * 16 + a_row) * A3STR + a_col);
#pragma unroll
        for (int kss = 0; kss < 4; kss++)
            ldsm_x4(qf[kss], qb + kss * 32);
    }

    float oacc[8][4];
#pragma unroll
    for (int nt = 0; nt < 8; nt++)
#pragma unroll
        for (int j = 0; j < 4; j++) oacc[nt][j] = 0.f;

    float m0 = -INFINITY, m1 = -INFINITY, l0 = 0.f, l1 = 0.f;

    int kt0 = 0, ktend = nk;
    if (mode == 0) { kt0 = (q0 > 511) ? ((q0 - 511) & ~63) : 0; ktend = q0 + 128; }

    const int klr = tid >> 3, klc = (tid & 7) * 8;

    for (int kt = kt0; kt < ktend; kt += 64) {
        __syncthreads();
        {
            size_t gb = (size_t)(b * nk + kt + klr) * ks + h * HDIM + klc;
            size_t step = (size_t)32 * ks;
#pragma unroll
            for (int i = 0; i < 2; i++) {
                *(uint4*)(sKh + (klr + i * 32) * A3STR + klc) = *(const uint4*)(Kh + gb + i * step);
                *(uint4*)(sKl + (klr + i * 32) * A3STR + klc) = *(const uint4*)(Kl + gb + i * step);
                *(uint4*)(sVh + (klr + i * 32) * A3STR + klc) = *(const uint4*)(Vh + gb + i * step);
            }
        }
        __syncthreads();

        float sacc[8][4];
#pragma unroll
        for (int nt = 0; nt < 8; nt++)
#pragma unroll
            for (int j = 0; j < 4; j++) sacc[nt][j] = 0.f;

        const uint32_t khb = smem_u32(sKh + b_row * A3STR + b_col);
        const uint32_t klb = smem_u32(sKl + b_row * A3STR + b_col);
#pragma unroll
        for (int kss = 0; kss < 4; kss++) {
            const int k0b = kss * 32;
#pragma unroll
            for (int pr = 0; pr < 4; pr++) {
                uint32_t kh[4];
                ldsm_x4(kh, khb + pr * (16 * A3STR * 2) + k0b);
                mma16816(sacc[2 * pr],     qf[kss], kh[0], kh[1]);
                mma16816(sacc[2 * pr + 1], qf[kss], kh[2], kh[3]);
            }
#pragma unroll
            for (int pr = 0; pr < 4; pr++) {
                uint32_t kl[4];
                ldsm_x4(kl, klb + pr * (16 * A3STR * 2) + k0b);
                mma16816(sacc[2 * pr],     qf[kss], kl[0], kl[1]);
                mma16816(sacc[2 * pr + 1], qf[kss], kl[2], kl[3]);
            }
        }

        // ---- mask (arithmetic positions) + warp-local max ----
        float bx0 = -INFINITY, bx1 = -INFINITY;
#pragma unroll
        for (int nt = 0; nt < 8; nt++) {
#pragma unroll
            for (int ci = 0; ci < 2; ci++) {
                int j = nt * 8 + lc + ci;
                int p = (mode == 0) ? (kt + j)
                      : (mode == 1) ? (kt + j + 1) * 8
                                    : pos[j];
                bool v0 = (mode == 0) ? ((unsigned)(qq0 - p) < 512u) : (qq0 >= p);
                bool v1 = (mode == 0) ? ((unsigned)(qq1 - p) < 512u) : (qq1 >= p);
                if (!v0) sacc[nt][ci] = NEGBIG;
                if (!v1) sacc[nt][2 + ci] = NEGBIG;
                bx0 = fmaxf(bx0, sacc[nt][ci]);
                bx1 = fmaxf(bx1, sacc[nt][2 + ci]);
            }
        }
        bx0 = fmaxf(bx0, __shfl_xor_sync(0xffffffffu, bx0, 1));
        bx0 = fmaxf(bx0, __shfl_xor_sync(0xffffffffu, bx0, 2));
        bx1 = fmaxf(bx1, __shfl_xor_sync(0xffffffffu, bx1, 1));
        bx1 = fmaxf(bx1, __shfl_xor_sync(0xffffffffu, bx1, 2));
        float mn0 = fmaxf(m0, bx0), mn1 = fmaxf(m1, bx1);

        // ---- fast exp + pack P as A-frags ----
        uint32_t pr0[8], pr1[8];
        float lt0 = 0.f, lt1 = 0.f;
#pragma unroll
        for (int nt = 0; nt < 8; nt++) {
            float e0 = __expf(sacc[nt][0] - mn0), e1 = __expf(sacc[nt][1] - mn0);
            float e2 = __expf(sacc[nt][2] - mn1), e3 = __expf(sacc[nt][3] - mn1);
            lt0 += e0 + e1; lt1 += e2 + e3;
            __half2 hp0 = __halves2half2(__float2half(e0), __float2half(e1));
            __half2 hp1 = __halves2half2(__float2half(e2), __float2half(e3));
            pr0[nt] = *(uint32_t*)&hp0;
            pr1[nt] = *(uint32_t*)&hp1;
        }
        lt0 += __shfl_xor_sync(0xffffffffu, lt0, 1);
        lt0 += __shfl_xor_sync(0xffffffffu, lt0, 2);
        lt1 += __shfl_xor_sync(0xffffffffu, lt1, 1);
        lt1 += __shfl_xor_sync(0xffffffffu, lt1, 2);

        float al0 = __expf(m0 - mn0), al1 = __expf(m1 - mn1);
        m0 = mn0; m1 = mn1;
        l0 = l0 * al0 + lt0;
        l1 = l1 * al1 + lt1;
#pragma unroll
        for (int nt = 0; nt < 8; nt++) {
            oacc[nt][0] *= al0; oacc[nt][1] *= al0;
            oacc[nt][2] *= al1; oacc[nt][3] *= al1;
        }

        const uint32_t vb = smem_u32(sVh + v_row * A3STR + v_col);
#pragma unroll
        for (int kb = 0; kb < 4; kb++) {
            uint32_t af[4] = { pr0[2 * kb], pr1[2 * kb], pr0[2 * kb + 1], pr1[2 * kb + 1] };
#pragma unroll
            for (int vt = 0; vt < 4; vt++) {
                uint32_t vh[4];
                ldsm_x4_t(vh, vb + kb * (16 * A3STR * 2) + vt * 32);
                mma16816(oacc[2 * vt],     af, vh[0], vh[1]);
                mma16816(oacc[2 * vt + 1], af, vh[2], vh[3]);
            }
        }
    }

    float i0 = 1.f / l0, i1 = 1.f / l1;
    __half* Oh = P.Oh[mode];
#pragma unroll
    for (int nt = 0; nt < 8; nt++) {
        int c = h * HDIM + nt * 8 + lc;
        size_t o0 = (size_t)(b * S_LEN + qq0) * 512 + c;
        size_t o1 = (size_t)(b * S_LEN + qq1) * 512 + c;
        *(__half2*)(Oh + o0) = __halves2half2(
            __float2half(oacc[nt][0] * i0), __float2half(oacc[nt][1] * i0));
        *(__half2*)(Oh + o1) = __halves2half2(
            __float2half(oacc[nt][2] * i1), __float2half(oacc[nt][3] * i1));
    }
}

// ===================== fused topk + gather ==================================
__global__ __launch_bounds__(256) void topk_gather(
    const float* __restrict__ imp, const float* __restrict__ x,
    int* __restrict__ tidx, __half* __restrict__ sh)
{
    int b = blockIdx.x;
    __shared__ float v[2048];
    __shared__ float wv[8];
    __shared__ int   wi[8];
    __shared__ int   sel[64];
    const int tid = threadIdx.x, lane = tid & 31, wid = tid >> 5;

    for (int i = tid; i < 2048; i += 256) v[i] = imp[b * 2048 + i];
    __syncthreads();

    for (int r = 0; r < 64; r++) {
        float bv = -INFINITY; int bi = 0x7fffffff;
        for (int i = tid; i < 2048; i += 256) {
            float xv = v[i];
            if (xv > bv) { bv = xv; bi = i; }
        }
#pragma unroll
        for (int off = 16; off; off >>= 1) {
            float ov = __shfl_xor_sync(0xffffffffu, bv, off);
            int   oi = __shfl_xor_sync(0xffffffffu, bi, off);
            if (ov > bv || (ov == bv && oi < bi)) { bv = ov; bi = oi; }
        }
        if (!lane) { wv[wid] = bv; wi[wid] = bi; }
        __syncthreads();
        if (wid == 0) {
            float cv = (lane < 8) ? wv[lane] : -INFINITY;
            int   ci = (lane < 8) ? wi[lane] : 0x7fffffff;
#pragma unroll
            for (int off = 4; off; off >>= 1) {
                float ov = __shfl_xor_sync(0xffffffffu, cv, off);
                int   oi = __shfl_xor_sync(0xffffffffu, ci, off);
                if (ov > cv || (ov == cv && oi < ci)) { cv = ov; ci = oi; }
            }
            if (!lane) { sel[r] = ci; tidx[b * 64 + r] = ci; v[ci] = -INFINITY; }
        }
        __syncthreads();
    }

    for (int r = 0; r < 64; r++) {
        int src = sel[r];
        for (int d = tid; d < 512; d += 256)
            sh[(size_t)(b * 64 + r) * 512 + d] =
                __float2half(x[(size_t)(b * S_LEN + src) * 512 + d]);
    }
}

__global__ void combine_kernel(const float* __restrict__ b0, const float* __restrict__ bC,
                               const float* __restrict__ bT, float* __restrict__ out)
{
    int i = (blockIdx.x * 256 + threadIdx.x) * 4;
    float4 v0 = *(const float4*)(b0 + i);
    float4 vC = *(const float4*)(bC + i);
    float4 vT = *(const float4*)(bT + i);
    v0.x += vC.x + vT.x;
    v0.y += vC.y + vT.y;
    v0.z += vC.z + vT.z;
    v0.w += vC.w + vT.w;
    *(float4*)(out + i) = v0;
}

// ===================== launch ===============================================
extern "C" void kernel_launch(void* const* d_in, const int* in_sizes, int n_in,
                              void* d_out, int out_size)
{
    const float* x    = (const float*)d_in[0];
    const float* Wqkv = (const float*)d_in[1];  const float* bqkv = (const float*)d_in[2];
    const float* Wlo  = (const float*)d_in[3];  const float* blo  = (const float*)d_in[4];
    const float* Wcq  = (const float*)d_in[5];  const float* bcq  = (const float*)d_in[6];
    const float* Wck  = (const float*)d_in[7];  const float* bck  = (const float*)d_in[8];
    const float* Wcv  = (const float*)d_in[9];  const float* bcv  = (const float*)d_in[10];
    const float* Wco  = (const float*)d_in[11]; const float* bco  = (const float*)d_in[12];
    const float* Wgc  = (const float*)d_in[13]; const float* bgc  = (const float*)d_in[14];
    const float* Wimp = (const float*)d_in[15]; const float* bimp = (const float*)d_in[16];
    const float* Wtq  = (const float*)d_in[17]; const float* btq  = (const float*)d_in[18];
    const float* Wtk  = (const float*)d_in[19]; const float* btk  = (const float*)d_in[20];
    const float* Wtv  = (const float*)d_in[21]; const float* btv  = (const float*)d_in[22];
    const float* Wto  = (const float*)d_in[23]; const float* bto  = (const float*)d_in[24];
    const float* Wgt  = (const float*)d_in[25]; const float* bgt  = (const float*)d_in[26];
    float* out = (float*)d_out;

    float *obuf, *gatec, *gatet, *imp;
    int* tidx;
    __half *xh, *qkvh, *qkvl, *qch, *qth, *aLh, *aCh, *aTh;
    __half *ch, *sh, *kch, *kcl, *vch, *kth, *ktl, *vth, *wh;
    cudaGetSymbolAddress((void**)&obuf,  g_obuf);
    cudaGetSymbolAddress((void**)&gatec, g_gatec);
    cudaGetSymbolAddress((void**)&gatet, g_gatet);
    cudaGetSymbolAddress((void**)&imp,   g_imp);
    cudaGetSymbolAddress((void**)&tidx,  g_tidx);
    cudaGetSymbolAddress((void**)&xh,   g_xh);
    cudaGetSymbolAddress((void**)&qkvh, g_qkvh); cudaGetSymbolAddress((void**)&qkvl, g_qkvl);
    cudaGetSymbolAddress((void**)&qch,  g_qch);
    cudaGetSymbolAddress((void**)&qth,  g_qth);
    cudaGetSymbolAddress((void**)&aLh,  g_aLh);
    cudaGetSymbolAddress((void**)&aCh,  g_aCh);
    cudaGetSymbolAddress((void**)&aTh,  g_aTh);
    cudaGetSymbolAddress((void**)&ch,   g_ch);
    cudaGetSymbolAddress((void**)&sh,   g_sh);
    cudaGetSymbolAddress((void**)&kch,  g_kch);  cudaGetSymbolAddress((void**)&kcl,  g_kcl);
    cudaGetSymbolAddress((void**)&vch,  g_vch);
    cudaGetSymbolAddress((void**)&kth,  g_kth);  cudaGetSymbolAddress((void**)&ktl,  g_ktl);
    cudaGetSymbolAddress((void**)&vth,  g_vth);
    cudaGetSymbolAddress((void**)&wh,   g_wh);

    const int ATTN_SMEM = (128 + 3 * 64) * A3STR * 2 + 64 * 4;
    cudaFuncSetAttribute(attn_mma, cudaFuncAttributeMaxDynamicSharedMemorySize, ATTN_SMEM);
    const int GEMM_SMEM = 2 * BUFSZ * 2;
    cudaFuncSetAttribute(mma_gemm, cudaFuncAttributeMaxDynamicSharedMemorySize, GEMM_SMEM);

    const int O_QKV = 0,    O_LO = 1536, O_CQ = 2048, O_CK = 2560, O_CV = 3072,
              O_CO = 3584,  O_GC = 4096, O_TQ = 4608, O_TK = 5120, O_TV = 5632,
              O_TO = 6144,  O_GT = 6656;
    #define WH(o) (wh + (size_t)(o) * 512)

    {
        PrepArgs A;
        A.x = x; A.Wimp = Wimp; A.bimp = bimp;
        A.xh = xh; A.ch = ch; A.imp = imp;
        A.s[0]  = {Wqkv, WH(O_QKV), 1536, 384};
        A.s[1]  = {Wlo,  WH(O_LO),  512, 128};
        A.s[2]  = {Wcq,  WH(O_CQ),  512, 128};
        A.s[3]  = {Wck,  WH(O_CK),  512, 128};
        A.s[4]  = {Wcv,  WH(O_CV),  512, 128};
        A.s[5]  = {Wco,  WH(O_CO),  512, 128};
        A.s[6]  = {Wgc,  WH(O_GC),  512, 128};
        A.s[7]  = {Wtq,  WH(O_TQ),  512, 128};
        A.s[8]  = {Wtk,  WH(O_TK),  512, 128};
        A.s[9]  = {Wtv,  WH(O_TV),  512, 128};
        A.s[10] = {Wto,  WH(O_TO),  512, 128};
        A.s[11] = {Wgt,  WH(O_GT),  512, 128};
        A.nseg = 12;
        prep_kernel<<<512 + 384 + 11 * 128, 512>>>(A);
    }
    topk_gather<<<2, 256>>>(imp, x, tidx, sh);

    {
        MBatch mb;
        mb.s[0] = {xh, WH(O_QKV), bqkv, nullptr, qkvh, qkvl, nullptr, 24, 32, 4, 1536};
        mb.s[1] = {xh, WH(O_CQ),  bcq,  nullptr, qch,  nullptr, nullptr, 8, 32, 3, 512};
        mb.s[2] = {xh, WH(O_GC),  bgc,  gatec,  nullptr, nullptr, nullptr, 8, 32, 1, 512};
        mb.s[3] = {xh, WH(O_TQ),  btq,  nullptr, qth,  nullptr, nullptr, 8, 32, 3, 512};
        mb.s[4] = {xh, WH(O_GT),  bgt,  gatet,  nullptr, nullptr, nullptr, 8, 32, 1, 512};
        mb.s[5] = {ch, WH(O_CK),  bck,  nullptr, kch,  kcl, nullptr, 8, 3, 2, 512};
        mb.s[6] = {ch, WH(O_CV),  bcv,  nullptr, vch,  nullptr, nullptr, 8, 3, 5, 512};
        mb.s[7] = {sh, WH(O_TK),  btk,  nullptr, kth,  ktl, nullptr, 8, 1, 2, 512};
        mb.s[8] = {sh, WH(O_TV),  btv,  nullptr, vth,  nullptr, nullptr, 8, 1, 5, 512};
        mb.n = 9;
        mma_gemm<<<1856, 256, GEMM_SMEM>>>(mb);
    }

    {
        AttnParams P;
        P.Qh[0] = qkvh;
        P.Kh[0] = qkvh + 512;  P.Kl[0] = qkvl + 512;
        P.Vh[0] = qkvh + 1024;
        P.Oh[0] = aLh; P.qs[0] = 1536; P.ks[0] = 1536; P.nk[0] = 2048;
        P.Qh[1] = qch; P.Kh[1] = kch; P.Kl[1] = kcl; P.Vh[1] = vch;
        P.Oh[1] = aCh; P.qs[1] = 512; P.ks[1] = 512; P.nk[1] = 192;
        P.Qh[2] = qth; P.Kh[2] = kth; P.Kl[2] = ktl; P.Vh[2] = vth;
        P.Oh[2] = aTh; P.qs[2] = 512; P.ks[2] = 512; P.nk[2] = 64;
        P.tidx = tidx;
        attn_mma<<<dim3(16, 8, 6), 256, ATTN_SMEM>>>(P);
    }

    float* buf0 = obuf;
    float* bufC = obuf + (size_t)NTOK * 512;
    float* bufT = obuf + (size_t)NTOK * 1024;
    {
        MBatch mb;
        mb.s[0] = {aLh, WH(O_LO), blo, buf0, nullptr, nullptr, nullptr, 8, 32, 0, 512};
        mb.s[1] = {aCh, WH(O_CO), bco, bufC, nullptr, nullptr, gatec,  8, 32, 6, 512};
        mb.s[2] = {aTh, WH(O_TO), bto, bufT, nullptr, nullptr, gatet,  8, 32, 6, 512};
        mb.n = 3;
        mma_gemm<<<768, 256, GEMM_SMEM>>>(mb);
    }
    combine_kernel<<<NTOK * 512 / 1024, 256>>>(buf0, bufC, bufT, out);
}